// round 6
// baseline (speedup 1.0000x reference)
#include <cuda_runtime.h>
#include <cuda_bf16.h>
#include <math.h>
#include <stdint.h>

#define BATCHN 2
#define SEQLENN 4096
#define DIMN 1024
#define DSTATE 64
#define DCONVN 4
#define DINNER 2048
#define NHEADSN 32
#define CONVD 2176          // D_INNER + 2*D_STATE
#define DPROJ 4256          // 2*D_INNER + 2*D_STATE + NHEADS
#define NROWS (BATCHN*SEQLENN)   // 8192
#define NSEG 16
#define SEGL (SEQLENN/NSEG) // 256
#define SCH 16              // timesteps per scan chunk
#define EPSV 1e-5f

// ------------------------- scratch -------------------------
__device__ float g_zxbcdt[(size_t)NROWS * DPROJ];
__device__ float g_xBCc[(size_t)NROWS * CONVD];
__device__ float g_dt[(size_t)NROWS * NHEADSN];
__device__ float g_y[(size_t)NROWS * DINNER];
__device__ float g_state[(size_t)BATCHN * NHEADSN * NSEG * DSTATE * 64];
__device__ float g_hin[(size_t)BATCHN * NHEADSN * NSEG * DSTATE * 64];
__device__ float g_acum[(size_t)BATCHN * NHEADSN * SEQLENN];

// packed bf16 hi/lo operands (uint32 = 2 bf16 along K)
__device__ uint32_t g_Xh[(size_t)NROWS * (DIMN/2)],   g_Xl[(size_t)NROWS * (DIMN/2)];
__device__ uint32_t g_Wih[(size_t)DPROJ * (DIMN/2)],  g_Wil[(size_t)DPROJ * (DIMN/2)];
__device__ uint32_t g_Woh[(size_t)DIMN * (DINNER/2)], g_Wol[(size_t)DIMN * (DINNER/2)];
__device__ uint32_t g_Wth[(size_t)DINNER * (DIMN/2)], g_Wtl[(size_t)DINNER * (DIMN/2)];
__device__ uint32_t g_ynh[(size_t)NROWS * (DINNER/2)],g_ynl[(size_t)NROWS * (DINNER/2)];
__device__ uint32_t g_Hh[(size_t)NROWS * (DIMN/2)],   g_Hl[(size_t)NROWS * (DIMN/2)];

// ------------------------- helpers -------------------------
__device__ __forceinline__ uint32_t pack_hi(float a, float b, float& ra, float& rb) {
    __nv_bfloat162 h = __floats2bfloat162_rn(a, b);
    ra = a - __bfloat162float(h.x);
    rb = b - __bfloat162float(h.y);
    return *(uint32_t*)&h;
}
__device__ __forceinline__ uint32_t pack_lo(float a, float b) {
    __nv_bfloat162 h = __floats2bfloat162_rn(a, b);
    return *(uint32_t*)&h;
}
__device__ __forceinline__ unsigned sptr(const void* p) {
    return (unsigned)__cvta_generic_to_shared(p);
}

#define MMA_BF16(c, a, b) \
    asm volatile("mma.sync.aligned.m16n8k16.row.col.f32.bf16.bf16.f32 " \
        "{%0,%1,%2,%3}, {%4,%5,%6,%7}, {%8,%9}, {%0,%1,%2,%3};" \
        : "+f"((c)[0]), "+f"((c)[1]), "+f"((c)[2]), "+f"((c)[3]) \
        : "r"((a)[0]), "r"((a)[1]), "r"((a)[2]), "r"((a)[3]), \
          "r"((b)[0]), "r"((b)[1]))

#define LDSM_X4(d, addr) \
    asm volatile("ldmatrix.sync.aligned.m8n8.x4.shared.b16 {%0,%1,%2,%3}, [%4];" \
        : "=r"((d)[0]), "=r"((d)[1]), "=r"((d)[2]), "=r"((d)[3]) : "r"(addr))

// ------------------------- f32 -> packed bf16 hi/lo -------------------------
__global__ void pack_kernel(const float* __restrict__ src,
                            uint32_t* __restrict__ hi, uint32_t* __restrict__ lo, int n4)
{
    int i = blockIdx.x * blockDim.x + threadIdx.x;
    if (i >= n4) return;
    float4 v = ((const float4*)src)[i];
    float r0, r1, r2, r3;
    uint32_t h0 = pack_hi(v.x, v.y, r0, r1);
    uint32_t h1 = pack_hi(v.z, v.w, r2, r3);
    ((uint2*)hi)[i] = make_uint2(h0, h1);
    ((uint2*)lo)[i] = make_uint2(pack_lo(r0, r1), pack_lo(r2, r3));
}

// ------------------------- GEMM on packed bf16: C[M,N] = A[M,K] @ B[N,K]^T -------------------------
// MODE 0: f32 C (guard gc<N).  MODE 1: packed hi/lo C.  MODE 2: f32 out with HK|HV split.
// 128x128 tile, 8 warps (2x4), K-step 16 (8 kpairs). ldmatrix fragments, stride-12 smem.
template<int MODE>
__global__ __launch_bounds__(256) void gemm_bf16(
    const uint32_t* __restrict__ Ahg, const uint32_t* __restrict__ Alg,
    const uint32_t* __restrict__ Bhg, const uint32_t* __restrict__ Blg,
    float* __restrict__ Cf, uint32_t* __restrict__ Ch, uint32_t* __restrict__ Cl,
    int M, int N, int K)
{
    __shared__ uint32_t Ash[128][12];
    __shared__ uint32_t Asl[128][12];
    __shared__ uint32_t Bsh[128][12];
    __shared__ uint32_t Bsl[128][12];

    const int tid  = threadIdx.x;
    const int bm   = blockIdx.y * 128;
    const int bn   = blockIdx.x * 128;
    const int lane = tid & 31;
    const int warp = tid >> 5;
    const int wm   = (warp >> 2) * 64;
    const int wn   = (warp & 3) * 32;
    const int grp  = lane >> 2;
    const int qid  = lane & 3;
    const int K2   = K >> 1;

    // staging: row = tid&127, col-quad = (tid>>7)*4
    const int sr = tid & 127;
    const int sc = (tid >> 7) * 4;
    const bool bok = (bn + sr) < N;
    const size_t aoff = (size_t)(bm + sr) * K2 + sc;
    const size_t boff = (size_t)(bn + sr) * K2 + sc;

    float acc[4][4][4];
#pragma unroll
    for (int i = 0; i < 4; i++)
#pragma unroll
        for (int j = 0; j < 4; j++)
#pragma unroll
            for (int e = 0; e < 4; e++) acc[i][j][e] = 0.f;

    const uint4 z4 = make_uint4(0, 0, 0, 0);
    uint4 avh, avl, bvh, bvl;
    avh = *(const uint4*)(Ahg + aoff);
    avl = *(const uint4*)(Alg + aoff);
    bvh = bok ? *(const uint4*)(Bhg + boff) : z4;
    bvl = bok ? *(const uint4*)(Blg + boff) : z4;

    for (int kb = 0; kb < K2; kb += 8) {
        *(uint4*)&Ash[sr][sc] = avh;
        *(uint4*)&Asl[sr][sc] = avl;
        *(uint4*)&Bsh[sr][sc] = bvh;
        *(uint4*)&Bsl[sr][sc] = bvl;
        __syncthreads();

        if (kb + 8 < K2) {
            avh = *(const uint4*)(Ahg + aoff + kb + 8);
            avl = *(const uint4*)(Alg + aoff + kb + 8);
            bvh = bok ? *(const uint4*)(Bhg + boff + kb + 8) : z4;
            bvl = bok ? *(const uint4*)(Blg + boff + kb + 8) : z4;
        }

        uint32_t ah[4][4], al[4][4], bhf[2][4], blf[2][4];
        const int arow = (lane & 15);
        const int acol = (lane >> 4) * 4;
#pragma unroll
        for (int mf = 0; mf < 4; mf++) {
            LDSM_X4(ah[mf], sptr(&Ash[wm + mf * 16 + arow][acol]));
            LDSM_X4(al[mf], sptr(&Asl[wm + mf * 16 + arow][acol]));
        }
        const int brow = (lane & 7) + ((lane >> 3) & 1) * 8;
        const int bcol = (lane >> 4) * 4;
#pragma unroll
        for (int pr = 0; pr < 2; pr++) {
            LDSM_X4(bhf[pr], sptr(&Bsh[wn + pr * 16 + brow][bcol]));
            LDSM_X4(blf[pr], sptr(&Bsl[wn + pr * 16 + brow][bcol]));
        }
#pragma unroll
        for (int mf = 0; mf < 4; mf++)
#pragma unroll
            for (int nf = 0; nf < 4; nf++) {
                const int pr = nf >> 1, e = nf & 1;
                uint32_t bh2[2] = { bhf[pr][e], bhf[pr][e + 2] };
                uint32_t bl2[2] = { blf[pr][e], blf[pr][e + 2] };
                MMA_BF16(acc[mf][nf], ah[mf], bh2);
                MMA_BF16(acc[mf][nf], ah[mf], bl2);
                MMA_BF16(acc[mf][nf], al[mf], bh2);
            }
        __syncthreads();
    }

#pragma unroll
    for (int mf = 0; mf < 4; mf++) {
        int gr0 = bm + wm + mf * 16 + grp;
        int gr1 = gr0 + 8;
#pragma unroll
        for (int nf = 0; nf < 4; nf++) {
            int gc = bn + wn + nf * 8 + 2 * qid;
            if (MODE == 0) {
                if (gc < N) {
                    Cf[(size_t)gr0 * N + gc]     = acc[mf][nf][0];
                    Cf[(size_t)gr0 * N + gc + 1] = acc[mf][nf][1];
                    Cf[(size_t)gr1 * N + gc]     = acc[mf][nf][2];
                    Cf[(size_t)gr1 * N + gc + 1] = acc[mf][nf][3];
                }
            } else if (MODE == 1) {
                int kp = gc >> 1;
                float r0, r1;
                Ch[(size_t)gr0 * (N/2) + kp] = pack_hi(acc[mf][nf][0], acc[mf][nf][1], r0, r1);
                Cl[(size_t)gr0 * (N/2) + kp] = pack_lo(r0, r1);
                Ch[(size_t)gr1 * (N/2) + kp] = pack_hi(acc[mf][nf][2], acc[mf][nf][3], r0, r1);
                Cl[(size_t)gr1 * (N/2) + kp] = pack_lo(r0, r1);
            } else {
                size_t off = (gc < DIMN)
                    ? (size_t)gr0 * DIMN + gc
                    : (size_t)NROWS * DIMN + (size_t)gr0 * DIMN + (gc - DIMN);
                Cf[off]     = acc[mf][nf][0];
                Cf[off + 1] = acc[mf][nf][1];
                size_t off1 = off + (size_t)8 * DIMN;
                Cf[off1]     = acc[mf][nf][2];
                Cf[off1 + 1] = acc[mf][nf][3];
            }
        }
    }
}

// ------------------------- dt = softplus(dt_raw + dt_bias) -------------------------
__global__ void dt_kernel(const float* __restrict__ dt_bias)
{
    int idx = blockIdx.x * blockDim.x + threadIdx.x;
    if (idx >= NROWS * NHEADSN) return;
    int h = idx & (NHEADSN - 1);
    int row = idx >> 5;
    float v = g_zxbcdt[(size_t)row * DPROJ + (DINNER + CONVD) + h] + dt_bias[h];
    float sp = (v > 20.f) ? v : log1pf(expf(v));
    g_dt[idx] = sp;
}

// ------------------------- depthwise causal conv (w=4) + bias + SiLU -------------------------
__global__ void conv_silu_kernel(const float* __restrict__ cw, const float* __restrict__ cb)
{
    size_t idx = (size_t)blockIdx.x * blockDim.x + threadIdx.x;
    if (idx >= (size_t)NROWS * CONVD) return;
    int c = (int)(idx % CONVD);
    size_t bl = idx / CONVD;
    int l = (int)(bl % SEQLENN);
    int b = (int)(bl / SEQLENN);
    float acc = cb[c];
#pragma unroll
    for (int k = 0; k < DCONVN; k++) {
        int lt = l - (DCONVN - 1) + k;
        if (lt >= 0)
            acc = fmaf(cw[c * DCONVN + k],
                       g_zxbcdt[(size_t)(b * SEQLENN + lt) * DPROJ + DINNER + c], acc);
    }
    float sg = 1.f / (1.f + expf(-acc));
    g_xBCc[idx] = acc * sg;
}

// ------------------------- pass 1: per-segment local scan (STS-reduce, no shfl) -------------------------
__global__ __launch_bounds__(256) void scan_seg_kernel(const float* __restrict__ A_log)
{
    const int bid = blockIdx.x;
    const int seg = bid & (NSEG - 1);
    const int h   = (bid >> 4) & (NHEADSN - 1);
    const int b   = bid >> 9;
    const int tid = threadIdx.x;
    const int p   = tid >> 2;
    const int sub = tid & 3;
    const float Ah = -expf(A_log[h]);
    const int bh = b * NHEADSN + h;
    const int rbase = b * SEQLENN + seg * SEGL;

    __shared__ __align__(16) float s_x[SCH][64];
    __shared__ __align__(16) float s_B[SCH][64];
    __shared__ __align__(16) float s_C[SCH][64];
    __shared__ __align__(16) float s_yp[SCH][256];
    __shared__ float s_dt[SCH];
    __shared__ float s_dA[SCH];
    __shared__ float s_ac[SCH];
    __shared__ float s_run;

    if (tid == 0) s_run = 1.f;

    float hreg[16];
#pragma unroll
    for (int j = 0; j < 16; j++) hreg[j] = 0.f;

    for (int t0 = 0; t0 < SEGL; t0 += SCH) {
        {
            int t = tid >> 4;
            int q = (tid & 15) << 2;
            size_t ro = (size_t)(rbase + t0 + t) * CONVD;
            *(float4*)&s_x[t][q] = *(const float4*)(g_xBCc + ro + h * 64 + q);
            *(float4*)&s_B[t][q] = *(const float4*)(g_xBCc + ro + DINNER + q);
            *(float4*)&s_C[t][q] = *(const float4*)(g_xBCc + ro + DINNER + DSTATE + q);
        }
        if (tid < SCH) {
            float dtv = g_dt[(size_t)(rbase + t0 + tid) * NHEADSN + h];
            s_dt[tid] = dtv;
            s_dA[tid] = expf(dtv * Ah);
        }
        __syncthreads();
        if (tid == 0) {
            float run = s_run;
#pragma unroll
            for (int t = 0; t < SCH; t++) { run *= s_dA[t]; s_ac[t] = run; }
            s_run = run;
        }
#pragma unroll 2
        for (int t = 0; t < SCH; t++) {
            float dA = s_dA[t];
            float dtx = s_dt[t] * s_x[t][p];
            const float4* Bq = (const float4*)&s_B[t][sub * 16];
            const float4* Cq = (const float4*)&s_C[t][sub * 16];
            float y0 = 0.f, y1 = 0.f, y2 = 0.f, y3 = 0.f;
            {
                float4 Bv = Bq[0], Cv = Cq[0];
                hreg[0] = fmaf(hreg[0], dA, dtx * Bv.x); y0 = fmaf(hreg[0], Cv.x, y0);
                hreg[1] = fmaf(hreg[1], dA, dtx * Bv.y); y1 = fmaf(hreg[1], Cv.y, y1);
                hreg[2] = fmaf(hreg[2], dA, dtx * Bv.z); y2 = fmaf(hreg[2], Cv.z, y2);
                hreg[3] = fmaf(hreg[3], dA, dtx * Bv.w); y3 = fmaf(hreg[3], Cv.w, y3);
            }
            {
                float4 Bv = Bq[1], Cv = Cq[1];
                hreg[4] = fmaf(hreg[4], dA, dtx * Bv.x); y0 = fmaf(hreg[4], Cv.x, y0);
                hreg[5] = fmaf(hreg[5], dA, dtx * Bv.y); y1 = fmaf(hreg[5], Cv.y, y1);
                hreg[6] = fmaf(hreg[6], dA, dtx * Bv.z); y2 = fmaf(hreg[6], Cv.z, y2);
                hreg[7] = fmaf(hreg[7], dA, dtx * Bv.w); y3 = fmaf(hreg[7], Cv.w, y3);
            }
            {
                float4 Bv = Bq[2], Cv = Cq[2];
                hreg[8]  = fmaf(hreg[8],  dA, dtx * Bv.x); y0 = fmaf(hreg[8],  Cv.x, y0);
                hreg[9]  = fmaf(hreg[9],  dA, dtx * Bv.y); y1 = fmaf(hreg[9],  Cv.y, y1);
                hreg[10] = fmaf(hreg[10], dA, dtx * Bv.z); y2 = fmaf(hreg[10], Cv.z, y2);
                hreg[11] = fmaf(hreg[11], dA, dtx * Bv.w); y3 = fmaf(hreg[11], Cv.w, y3);
            }
            {
                float4 Bv = Bq[3], Cv = Cq[3];
                hreg[12] = fmaf(hreg[12], dA, dtx * Bv.x); y0 = fmaf(hreg[12], Cv.x, y0);
                hreg[13] = fmaf(hreg[13], dA, dtx * Bv.y); y1 = fmaf(hreg[13], Cv.y, y1);
                hreg[14] = fmaf(hreg[14], dA, dtx * Bv.z); y2 = fmaf(hreg[14], Cv.z, y2);
                hreg[15] = fmaf(hreg[15], dA, dtx * Bv.w); y3 = fmaf(hreg[15], Cv.w, y3);
            }
            s_yp[t][tid] = (y0 + y1) + (y2 + y3);
        }
        __syncthreads();
#pragma unroll
        for (int it = 0; it < 4; it++) {
            int i = tid + it * 256;
            int tt = i >> 6, pp = i & 63;
            float4 v = *(float4*)&s_yp[tt][pp * 4];
            g_y[(size_t)(rbase + t0 + tt) * DINNER + h * 64 + pp] = (v.x + v.y) + (v.z + v.w);
        }
        if (tid < SCH)
            g_acum[(size_t)bh * SEQLENN + seg * SEGL + t0 + tid] = s_ac[tid];
        __syncthreads();
    }

    float* st = g_state + ((size_t)bh * NSEG + seg) * (64 * DSTATE) + p * DSTATE + sub * 16;
#pragma unroll
    for (int q = 0; q < 4; q++)
        *(float4*)(st + q * 4) = make_float4(hreg[q*4+0], hreg[q*4+1], hreg[q*4+2], hreg[q*4+3]);
}

// ------------------------- pass 2: prefix over segment states -------------------------
__global__ __launch_bounds__(256) void state_combine_kernel()
{
    const int bh = blockIdx.x;
    const int tid = threadIdx.x;
    const size_t base = (size_t)bh * NSEG * (64 * DSTATE);
    float4 hin[4];
#pragma unroll
    for (int q = 0; q < 4; q++) hin[q] = make_float4(0.f, 0.f, 0.f, 0.f);

    for (int seg = 1; seg < NSEG; seg++) {
        float ap = g_acum[(size_t)bh * SEQLENN + seg * SEGL - 1];
        const float4* sl = (const float4*)(g_state + base + (size_t)(seg - 1) * (64 * DSTATE) + tid * 16);
        float4* ho = (float4*)(g_hin + base + (size_t)seg * (64 * DSTATE) + tid * 16);
#pragma unroll
        for (int q = 0; q < 4; q++) {
            float4 s = sl[q];
            hin[q].x = fmaf(hin[q].x, ap, s.x);
            hin[q].y = fmaf(hin[q].y, ap, s.y);
            hin[q].z = fmaf(hin[q].z, ap, s.z);
            hin[q].w = fmaf(hin[q].w, ap, s.w);
            ho[q] = hin[q];
        }
    }
}

// ------------------------- pass 3 (MMA): y += (C .* acum) @ H_in^T -------------------------
__global__ __launch_bounds__(256) void carry_mma_kernel()
{
    const int bid = blockIdx.x;
    const int seg = 1 + (bid % (NSEG - 1));
    const int bh  = bid / (NSEG - 1);
    const int h   = bh & (NHEADSN - 1);
    const int b   = bh >> 5;
    const int rbase = b * SEQLENN + seg * SEGL;

    const int tid  = threadIdx.x;
    const int lane = tid & 31;
    const int warp = tid >> 5;
    const int wm   = (warp >> 1) * 64;
    const int wn   = (warp & 1) * 32;
    const int grp  = lane >> 2;
    const int qid  = lane & 3;

    __shared__ uint32_t Ah[8][264];
    __shared__ uint32_t Al[8][264];
    __shared__ uint32_t Bh2[32][72];
    __shared__ uint32_t Bl2[32][72];

    {
        const float* hi = g_hin + ((size_t)bh * NSEG + seg) * (64 * DSTATE);
        for (int i = tid; i < 64 * 32; i += 256) {
            int p  = i >> 5;
            int kp = i & 31;
            float a0 = hi[p * DSTATE + kp * 2];
            float a1 = hi[p * DSTATE + kp * 2 + 1];
            float r0, r1;
            Bh2[kp][p] = pack_hi(a0, a1, r0, r1);
            Bl2[kp][p] = pack_lo(r0, r1);
        }
    }

    float acc[4][4][4];
#pragma unroll
    for (int i = 0; i < 4; i++)
#pragma unroll
        for (int j = 0; j < 4; j++)
#pragma unroll
            for (int e = 0; e < 4; e++) acc[i][j][e] = 0.f;

    for (int k0 = 0; k0 < DSTATE; k0 += 16) {
#pragma unroll
        for (int ld = 0; ld < 4; ld++) {
            int idx = tid + ld * 256;
            int r = idx >> 2;
            int kk = (idx & 3) << 2;
            float al2 = g_acum[(size_t)bh * SEQLENN + seg * SEGL + r];
            float4 v = *(const float4*)(g_xBCc + (size_t)(rbase + r) * CONVD + DINNER + DSTATE + k0 + kk);
            v.x *= al2; v.y *= al2; v.z *= al2; v.w *= al2;
            int spp = kk >> 1;
            float r0, r1, r2, r3;
            Ah[spp    ][r] = pack_hi(v.x, v.y, r0, r1);
            Ah[spp + 1][r] = pack_hi(v.z, v.w, r2, r3);
            Al[spp    ][r] = pack_lo(r0, r1);
            Al[spp + 1][r] = pack_lo(r2, r3);
        }
        __syncthreads();

        const int kb = k0 >> 1;
        uint32_t ah[4][4], al[4][4];
#pragma unroll
        for (int mf = 0; mf < 4; mf++) {
            int r0 = wm + mf * 16 + grp;
            ah[mf][0] = Ah[qid    ][r0];
            ah[mf][1] = Ah[qid    ][r0 + 8];
            ah[mf][2] = Ah[qid + 4][r0];
            ah[mf][3] = Ah[qid + 4][r0 + 8];
            al[mf][0] = Al[qid    ][r0];
            al[mf][1] = Al[qid    ][r0 + 8];
            al[mf][2] = Al[qid + 4][r0];
            al[mf][3] = Al[qid + 4][r0 + 8];
        }
        uint32_t bh_[4][2], bl_[4][2];
#pragma unroll
        for (int nf = 0; nf < 4; nf++) {
            int c0 = wn + nf * 8 + grp;
            bh_[nf][0] = Bh2[kb + qid    ][c0];
            bh_[nf][1] = Bh2[kb + qid + 4][c0];
            bl_[nf][0] = Bl2[kb + qid    ][c0];
            bl_[nf][1] = Bl2[kb + qid + 4][c0];
        }
#pragma unroll
        for (int mf = 0; mf < 4; mf++)
#pragma unroll
            for (int nf = 0; nf < 4; nf++) {
                MMA_BF16(acc[mf][nf], ah[mf], bh_[nf]);
                MMA_BF16(acc[mf][nf], ah[mf], bl_[nf]);
                MMA_BF16(acc[mf][nf], al[mf], bh_[nf]);
            }
        __syncthreads();
    }

#pragma unroll
    for (int mf = 0; mf < 4; mf++) {
        int t0 = wm + mf * 16 + grp;
        int t1 = t0 + 8;
#pragma unroll
        for (int nf = 0; nf < 4; nf++) {
            int gp = wn + nf * 8 + 2 * qid;
            size_t o0 = (size_t)(rbase + t0) * DINNER + h * 64 + gp;
            size_t o1 = (size_t)(rbase + t1) * DINNER + h * 64 + gp;
            g_y[o0]     += acc[mf][nf][0];
            g_y[o0 + 1] += acc[mf][nf][1];
            g_y[o1]     += acc[mf][nf][2];
            g_y[o1 + 1] += acc[mf][nf][3];
        }
    }
}

// ------------------------- D*x, gate, RMSNorm -> packed bf16 hi/lo -------------------------
__global__ __launch_bounds__(256) void gate_norm_kernel(
    const float* __restrict__ Dp, const float* __restrict__ norm_w)
{
    const int row = blockIdx.x;
    const int tid = threadIdx.x;
    const int c0 = tid * 8;
    const int hh = c0 >> 6;

    float vals[8];
    float ss = 0.f;
    {
        const float4* yv = (const float4*)(g_y + (size_t)row * DINNER + c0);
        const float4* xv = (const float4*)(g_xBCc + (size_t)row * CONVD + c0);
        const float4* zv = (const float4*)(g_zxbcdt + (size_t)row * DPROJ + c0);
        float Dh = Dp[hh];
#pragma unroll
        for (int q = 0; q < 2; q++) {
            float4 y = yv[q], x = xv[q], z = zv[q];
            float a[4] = {y.x, y.y, y.z, y.w};
            float b[4] = {x.x, x.y, x.z, x.w};
            float g[4] = {z.x, z.y, z.z, z.w};
#pragma unroll
            for (int e = 0; e < 4; e++) {
                float yy = fmaf(Dh, b[e], a[e]);
                float gg = g[e] / (1.f + expf(-g[e]));
                float v = yy * gg;
                vals[q * 4 + e] = v;
                ss = fmaf(v, v, ss);
            }
        }
    }
    __shared__ float red[32];
    for (int o = 16; o; o >>= 1) ss += __shfl_down_sync(0xffffffffu, ss, o);
    if ((tid & 31) == 0) red[tid >> 5] = ss;
    __syncthreads();
    if (tid < 32) {
        float s2 = (tid < 8) ? red[tid] : 0.f;
        for (int o = 4; o; o >>= 1) s2 += __shfl_down_sync(0xffffffffu, s2, o);
        if (tid == 0) red[0] = s2;
    }
    __syncthreads();
    float scale = rsqrtf(red[0] / (float)DINNER + EPSV);

    uint32_t ho[4], lo[4];
#pragma unroll
    for (int j = 0; j < 4; j++) {
        float a = vals[2*j]     * scale * norm_w[c0 + 2*j];
        float b = vals[2*j + 1] * scale * norm_w[c0 + 2*j + 1];
        float r0, r1;
        ho[j] = pack_hi(a, b, r0, r1);
        lo[j] = pack_lo(r0, r1);
    }
    *(uint4*)(g_ynh + (size_t)row * (DINNER/2) + tid * 4) = *(uint4*)ho;
    *(uint4*)(g_ynl + (size_t)row * (DINNER/2) + tid * 4) = *(uint4*)lo;
}

// ------------------------- launch -------------------------
extern "C" void kernel_launch(void* const* d_in, const int* in_sizes, int n_in,
                              void* d_out, int out_size)
{
    const float* X          = (const float*)d_in[0];
    const float* in_proj_w  = (const float*)d_in[1];
    const float* conv_w     = (const float*)d_in[2];
    const float* conv_b     = (const float*)d_in[3];
    const float* dt_bias    = (const float*)d_in[4];
    const float* A_log      = (const float*)d_in[5];
    const float* Dp         = (const float*)d_in[6];
    const float* norm_w     = (const float*)d_in[7];
    const float* out_proj_w = (const float*)d_in[8];
    const float* to_h_w     = (const float*)d_in[9];
    float* out = (float*)d_out;

    float *zx;
    uint32_t *Xh, *Xl, *Wih, *Wil, *Woh, *Wol, *Wth, *Wtl, *ynh, *ynl, *Hh, *Hl;
    cudaGetSymbolAddress((void**)&zx,  g_zxbcdt);
    cudaGetSymbolAddress((void**)&Xh,  g_Xh);  cudaGetSymbolAddress((void**)&Xl,  g_Xl);
    cudaGetSymbolAddress((void**)&Wih, g_Wih); cudaGetSymbolAddress((void**)&Wil, g_Wil);
    cudaGetSymbolAddress((void**)&Woh, g_Woh); cudaGetSymbolAddress((void**)&Wol, g_Wol);
    cudaGetSymbolAddress((void**)&Wth, g_Wth); cudaGetSymbolAddress((void**)&Wtl, g_Wtl);
    cudaGetSymbolAddress((void**)&ynh, g_ynh); cudaGetSymbolAddress((void**)&ynl, g_ynl);
    cudaGetSymbolAddress((void**)&Hh,  g_Hh);  cudaGetSymbolAddress((void**)&Hl,  g_Hl);

    // 0) pack operands to bf16 hi/lo
    pack_kernel<<<(NROWS * DIMN / 4 + 255) / 256, 256>>>(X, Xh, Xl, NROWS * DIMN / 4);
    pack_kernel<<<(DPROJ * DIMN / 4 + 255) / 256, 256>>>(in_proj_w, Wih, Wil, DPROJ * DIMN / 4);
    pack_kernel<<<(DIMN * DINNER / 4 + 255) / 256, 256>>>(out_proj_w, Woh, Wol, DIMN * DINNER / 4);
    pack_kernel<<<(DINNER * DIMN / 4 + 255) / 256, 256>>>(to_h_w, Wth, Wtl, DINNER * DIMN / 4);

    // 1) zxbcdt = X @ in_proj_w^T
    gemm_bf16<0><<<dim3((DPROJ + 127) / 128, NROWS / 128), 256>>>(
        Xh, Xl, Wih, Wil, zx, nullptr, nullptr, NROWS, DPROJ, DIMN);
    // 2) dt
    dt_kernel<<<(NROWS * NHEADSN + 255) / 256, 256>>>(dt_bias);
    // 3) conv + silu
    conv_silu_kernel<<<(int)(((size_t)NROWS * CONVD + 255) / 256), 256>>>(conv_w, conv_b);
    // 4) segmented scan
    scan_seg_kernel<<<BATCHN * NHEADSN * NSEG, 256>>>(A_log);
    state_combine_kernel<<<BATCHN * NHEADSN, 256>>>();
    carry_mma_kernel<<<BATCHN * NHEADSN * (NSEG - 1), 256>>>();
    // 5) gate + rmsnorm -> packed yn
    gate_norm_kernel<<<NROWS, 256>>>(Dp, norm_w);
    // 6) H = yn @ out_proj_w^T  (packed out)
    gemm_bf16<1><<<dim3(DIMN / 128, NROWS / 128), 256>>>(
        ynh, ynl, Woh, Wol, nullptr, Hh, Hl, NROWS, DIMN, DINNER);
    // 7) HKV = H @ to_h_w^T with fused split
    gemm_bf16<2><<<dim3(DINNER / 128, NROWS / 128), 256>>>(
        Hh, Hl, Wth, Wtl, out, nullptr, nullptr, NROWS, DINNER, DIMN);
}

// round 8
// speedup vs baseline: 1.1193x; 1.1193x over previous
#include <cuda_runtime.h>
#include <cuda_bf16.h>
#include <cuda_fp16.h>
#include <math.h>
#include <stdint.h>

#define BATCHN 2
#define SEQLENN 4096
#define DIMN 1024
#define DSTATE 64
#define DCONVN 4
#define DINNER 2048
#define NHEADSN 32
#define CONVD 2176          // D_INNER + 2*D_STATE
#define DPROJ 4256          // 2*D_INNER + 2*D_STATE + NHEADS
#define NROWS (BATCHN*SEQLENN)   // 8192
#define NSEG 16
#define SEGL (SEQLENN/NSEG) // 256
#define TCH 32
#define SCH 16
#define EPSV 1e-5f

// ------------------------- scratch -------------------------
__device__ float g_zxbcdt[(size_t)NROWS * DPROJ];
__device__ float g_xBCc[(size_t)NROWS * CONVD];
__device__ float g_dt[(size_t)NROWS * NHEADSN];
__device__ float g_y[(size_t)NROWS * DINNER];
__device__ float g_state[(size_t)BATCHN * NHEADSN * NSEG * DSTATE * 64];
__device__ float g_hin[(size_t)BATCHN * NHEADSN * NSEG * DSTATE * 64];
__device__ float g_acum[(size_t)BATCHN * NHEADSN * SEQLENN];

// packed fp16 operands (uint32 = 2 halves along K)
__device__ uint32_t g_Woh[(size_t)DIMN * (DINNER/2)];
__device__ uint32_t g_Wth[(size_t)DINNER * (DIMN/2)];
__device__ uint32_t g_ynh[(size_t)NROWS * (DINNER/2)], g_ynl[(size_t)NROWS * (DINNER/2)];
__device__ uint32_t g_Hh[(size_t)NROWS * (DIMN/2)],    g_Hl[(size_t)NROWS * (DIMN/2)];

// ------------------------- bf16 helpers (GEMM1 / carry) -------------------------
__device__ __forceinline__ uint32_t pack_hi(float a, float b, float& ra, float& rb) {
    __nv_bfloat162 h = __floats2bfloat162_rn(a, b);
    ra = a - __bfloat162float(h.x);
    rb = b - __bfloat162float(h.y);
    return *(uint32_t*)&h;
}
__device__ __forceinline__ uint32_t pack_lo(float a, float b) {
    __nv_bfloat162 h = __floats2bfloat162_rn(a, b);
    return *(uint32_t*)&h;
}
// fp16 helpers (GEMM2/3)
__device__ __forceinline__ uint32_t packh_hi(float a, float b, float& ra, float& rb) {
    __half2 h = __floats2half2_rn(a, b);
    ra = a - __half2float(__low2half(h));
    rb = b - __half2float(__high2half(h));
    return *(uint32_t*)&h;
}
__device__ __forceinline__ uint32_t packh(float a, float b) {
    __half2 h = __floats2half2_rn(a, b);
    return *(uint32_t*)&h;
}

#define MMA_BF16(c, a, b) \
    asm volatile("mma.sync.aligned.m16n8k16.row.col.f32.bf16.bf16.f32 " \
        "{%0,%1,%2,%3}, {%4,%5,%6,%7}, {%8,%9}, {%0,%1,%2,%3};" \
        : "+f"((c)[0]), "+f"((c)[1]), "+f"((c)[2]), "+f"((c)[3]) \
        : "r"((a)[0]), "r"((a)[1]), "r"((a)[2]), "r"((a)[3]), \
          "r"((b)[0]), "r"((b)[1]))

#define MMA_F16(c, a, b) \
    asm volatile("mma.sync.aligned.m16n8k16.row.col.f32.f16.f16.f32 " \
        "{%0,%1,%2,%3}, {%4,%5,%6,%7}, {%8,%9}, {%0,%1,%2,%3};" \
        : "+f"((c)[0]), "+f"((c)[1]), "+f"((c)[2]), "+f"((c)[3]) \
        : "r"((a)[0]), "r"((a)[1]), "r"((a)[2]), "r"((a)[3]), \
          "r"((b)[0]), "r"((b)[1]))

// ------------------------- GEMM1: bf16 3-split, f32 in/out (R5-proven) -------------------------
__global__ __launch_bounds__(256) void gemm_nt_tc(
    const float* __restrict__ A, const float* __restrict__ B,
    float* __restrict__ C, int M, int N, int K)
{
    __shared__ uint32_t Ah[8][136];
    __shared__ uint32_t Al[8][136];
    __shared__ uint32_t Bh[8][136];
    __shared__ uint32_t Bl[8][136];

    const int tid  = threadIdx.x;
    const int bm   = blockIdx.y * 128;
    const int bn   = blockIdx.x * 128;
    const int lane = tid & 31;
    const int warp = tid >> 5;
    const int wm   = (warp >> 2) * 64;
    const int wn   = (warp & 3) * 32;
    const int grp  = lane >> 2;
    const int qid  = lane & 3;

    const int sr0 = tid >> 2;
    const int sr1 = sr0 + 64;
    const int skk = (tid & 3) << 2;
    const int spp = skk >> 1;

    float acc[4][4][4];
#pragma unroll
    for (int i = 0; i < 4; i++)
#pragma unroll
        for (int j = 0; j < 4; j++)
#pragma unroll
            for (int e = 0; e < 4; e++) acc[i][j][e] = 0.f;

    float4 av[2], bv[2];
    {
        const float4 z4 = make_float4(0.f, 0.f, 0.f, 0.f);
        av[0] = (bm + sr0 < M) ? *(const float4*)(A + (size_t)(bm + sr0) * K + skk) : z4;
        av[1] = (bm + sr1 < M) ? *(const float4*)(A + (size_t)(bm + sr1) * K + skk) : z4;
        bv[0] = (bn + sr0 < N) ? *(const float4*)(B + (size_t)(bn + sr0) * K + skk) : z4;
        bv[1] = (bn + sr1 < N) ? *(const float4*)(B + (size_t)(bn + sr1) * K + skk) : z4;
    }

    for (int k0 = 0; k0 < K; k0 += 16) {
#pragma unroll
        for (int half = 0; half < 2; half++) {
            int r = half ? sr1 : sr0;
            float4 v = av[half];
            float rx, ry, rz, rw;
            Ah[spp    ][r] = pack_hi(v.x, v.y, rx, ry);
            Ah[spp + 1][r] = pack_hi(v.z, v.w, rz, rw);
            Al[spp    ][r] = pack_lo(rx, ry);
            Al[spp + 1][r] = pack_lo(rz, rw);
            v = bv[half];
            Bh[spp    ][r] = pack_hi(v.x, v.y, rx, ry);
            Bh[spp + 1][r] = pack_hi(v.z, v.w, rz, rw);
            Bl[spp    ][r] = pack_lo(rx, ry);
            Bl[spp + 1][r] = pack_lo(rz, rw);
        }
        __syncthreads();

        if (k0 + 16 < K) {
            const float4 z4 = make_float4(0.f, 0.f, 0.f, 0.f);
            int kn = k0 + 16 + skk;
            av[0] = (bm + sr0 < M) ? *(const float4*)(A + (size_t)(bm + sr0) * K + kn) : z4;
            av[1] = (bm + sr1 < M) ? *(const float4*)(A + (size_t)(bm + sr1) * K + kn) : z4;
            bv[0] = (bn + sr0 < N) ? *(const float4*)(B + (size_t)(bn + sr0) * K + kn) : z4;
            bv[1] = (bn + sr1 < N) ? *(const float4*)(B + (size_t)(bn + sr1) * K + kn) : z4;
        }

        uint32_t ah[4][4], al[4][4];
#pragma unroll
        for (int mf = 0; mf < 4; mf++) {
            int r0 = wm + mf * 16 + grp;
            ah[mf][0] = Ah[qid    ][r0];
            ah[mf][1] = Ah[qid    ][r0 + 8];
            ah[mf][2] = Ah[qid + 4][r0];
            ah[mf][3] = Ah[qid + 4][r0 + 8];
            al[mf][0] = Al[qid    ][r0];
            al[mf][1] = Al[qid    ][r0 + 8];
            al[mf][2] = Al[qid + 4][r0];
            al[mf][3] = Al[qid + 4][r0 + 8];
        }
        uint32_t bh[4][2], bl[4][2];
#pragma unroll
        for (int nf = 0; nf < 4; nf++) {
            int c0 = wn + nf * 8 + grp;
            bh[nf][0] = Bh[qid    ][c0];
            bh[nf][1] = Bh[qid + 4][c0];
            bl[nf][0] = Bl[qid    ][c0];
            bl[nf][1] = Bl[qid + 4][c0];
        }
#pragma unroll
        for (int mf = 0; mf < 4; mf++)
#pragma unroll
            for (int nf = 0; nf < 4; nf++) {
                MMA_BF16(acc[mf][nf], ah[mf], bh[nf]);
                MMA_BF16(acc[mf][nf], ah[mf], bl[nf]);
                MMA_BF16(acc[mf][nf], al[mf], bh[nf]);
            }
        __syncthreads();
    }

#pragma unroll
    for (int mf = 0; mf < 4; mf++) {
        int gr0 = bm + wm + mf * 16 + grp;
        int gr1 = gr0 + 8;
#pragma unroll
        for (int nf = 0; nf < 4; nf++) {
            int gc = bn + wn + nf * 8 + 2 * qid;
            if (gc < N) {
                C[(size_t)gr0 * N + gc]     = acc[mf][nf][0];
                C[(size_t)gr0 * N + gc + 1] = acc[mf][nf][1];
                C[(size_t)gr1 * N + gc]     = acc[mf][nf][2];
                C[(size_t)gr1 * N + gc + 1] = acc[mf][nf][3];
            }
        }
    }
}

// ------------------------- GEMM2/3: fp16 2-MMA, packed operands -------------------------
// C = (Ah + Al) @ Bh^T.  MODE 1: packed fp16 hi/lo out.  MODE 2: f32 out with HK|HV split.
template<int MODE>
__global__ __launch_bounds__(256) void gemm_f16(
    const uint32_t* __restrict__ Ahg, const uint32_t* __restrict__ Alg,
    const uint32_t* __restrict__ Bhg,
    float* __restrict__ Cf, uint32_t* __restrict__ Ch, uint32_t* __restrict__ Cl,
    int M, int N, int K)
{
    __shared__ uint32_t Ah[8][136];
    __shared__ uint32_t Al[8][136];
    __shared__ uint32_t Bh[8][136];

    const int tid  = threadIdx.x;
    const int bm   = blockIdx.y * 128;
    const int bn   = blockIdx.x * 128;
    const int lane = tid & 31;
    const int warp = tid >> 5;
    const int wm   = (warp >> 2) * 64;
    const int wn   = (warp & 3) * 32;
    const int grp  = lane >> 2;
    const int qid  = lane & 3;
    const int K2   = K >> 1;

    // staging: each thread handles 1 row, 4 kpairs for each of the 3 arrays
    const int sr = tid >> 1;          // 0..127
    const int sc = (tid & 1) * 4;     // 0 or 4
    const size_t aoff = (size_t)(bm + sr) * K2 + sc;
    const size_t boff = (size_t)(bn + sr) * K2 + sc;

    float acc[4][4][4];
#pragma unroll
    for (int i = 0; i < 4; i++)
#pragma unroll
        for (int j = 0; j < 4; j++)
#pragma unroll
            for (int e = 0; e < 4; e++) acc[i][j][e] = 0.f;

    uint4 avh = *(const uint4*)(Ahg + aoff);
    uint4 avl = *(const uint4*)(Alg + aoff);
    uint4 bvh = *(const uint4*)(Bhg + boff);

    for (int kb = 0; kb < K2; kb += 8) {
        Ah[sc + 0][sr] = avh.x; Ah[sc + 1][sr] = avh.y;
        Ah[sc + 2][sr] = avh.z; Ah[sc + 3][sr] = avh.w;
        Al[sc + 0][sr] = avl.x; Al[sc + 1][sr] = avl.y;
        Al[sc + 2][sr] = avl.z; Al[sc + 3][sr] = avl.w;
        Bh[sc + 0][sr] = bvh.x; Bh[sc + 1][sr] = bvh.y;
        Bh[sc + 2][sr] = bvh.z; Bh[sc + 3][sr] = bvh.w;
        __syncthreads();

        if (kb + 8 < K2) {
            avh = *(const uint4*)(Ahg + aoff + kb + 8);
            avl = *(const uint4*)(Alg + aoff + kb + 8);
            bvh = *(const uint4*)(Bhg + boff + kb + 8);
        }

        uint32_t ah[4][4], al[4][4];
#pragma unroll
        for (int mf = 0; mf < 4; mf++) {
            int r0 = wm + mf * 16 + grp;
            ah[mf][0] = Ah[qid    ][r0];
            ah[mf][1] = Ah[qid    ][r0 + 8];
            ah[mf][2] = Ah[qid + 4][r0];
            ah[mf][3] = Ah[qid + 4][r0 + 8];
            al[mf][0] = Al[qid    ][r0];
            al[mf][1] = Al[qid    ][r0 + 8];
            al[mf][2] = Al[qid + 4][r0];
            al[mf][3] = Al[qid + 4][r0 + 8];
        }
        uint32_t bh[4][2];
#pragma unroll
        for (int nf = 0; nf < 4; nf++) {
            int c0 = wn + nf * 8 + grp;
            bh[nf][0] = Bh[qid    ][c0];
            bh[nf][1] = Bh[qid + 4][c0];
        }
#pragma unroll
        for (int mf = 0; mf < 4; mf++)
#pragma unroll
            for (int nf = 0; nf < 4; nf++) {
                MMA_F16(acc[mf][nf], ah[mf], bh[nf]);
                MMA_F16(acc[mf][nf], al[mf], bh[nf]);
            }
        __syncthreads();
    }

#pragma unroll
    for (int mf = 0; mf < 4; mf++) {
        int gr0 = bm + wm + mf * 16 + grp;
        int gr1 = gr0 + 8;
#pragma unroll
        for (int nf = 0; nf < 4; nf++) {
            int gc = bn + wn + nf * 8 + 2 * qid;
            if (MODE == 1) {
                int kp = gc >> 1;
                float r0, r1;
                Ch[(size_t)gr0 * (N/2) + kp] = packh_hi(acc[mf][nf][0], acc[mf][nf][1], r0, r1);
                Cl[(size_t)gr0 * (N/2) + kp] = packh(r0, r1);
                Ch[(size_t)gr1 * (N/2) + kp] = packh_hi(acc[mf][nf][2], acc[mf][nf][3], r0, r1);
                Cl[(size_t)gr1 * (N/2) + kp] = packh(r0, r1);
            } else {
                size_t off = (gc < DIMN)
                    ? (size_t)gr0 * DIMN + gc
                    : (size_t)NROWS * DIMN + (size_t)gr0 * DIMN + (gc - DIMN);
                Cf[off]     = acc[mf][nf][0];
                Cf[off + 1] = acc[mf][nf][1];
                size_t off1 = off + (size_t)8 * DIMN;
                Cf[off1]     = acc[mf][nf][2];
                Cf[off1 + 1] = acc[mf][nf][3];
            }
        }
    }
}

// ------------------------- f32 -> packed fp16 (hi only) -------------------------
__global__ void pack_f16_kernel(const float* __restrict__ src, uint32_t* __restrict__ hi, int n4)
{
    int i = blockIdx.x * blockDim.x + threadIdx.x;
    if (i >= n4) return;
    float4 v = ((const float4*)src)[i];
    ((uint2*)hi)[i] = make_uint2(packh(v.x, v.y), packh(v.z, v.w));
}

// ------------------------- dt = softplus(dt_raw + dt_bias) -------------------------
__global__ void dt_kernel(const float* __restrict__ dt_bias)
{
    int idx = blockIdx.x * blockDim.x + threadIdx.x;
    if (idx >= NROWS * NHEADSN) return;
    int h = idx & (NHEADSN - 1);
    int row = idx >> 5;
    float v = g_zxbcdt[(size_t)row * DPROJ + (DINNER + CONVD) + h] + dt_bias[h];
    float sp = (v > 20.f) ? v : log1pf(expf(v));
    g_dt[idx] = sp;
}

// ------------------------- depthwise causal conv (w=4) + bias + SiLU -------------------------
__global__ void conv_silu_kernel(const float* __restrict__ cw, const float* __restrict__ cb)
{
    size_t idx = (size_t)blockIdx.x * blockDim.x + threadIdx.x;
    if (idx >= (size_t)NROWS * CONVD) return;
    int c = (int)(idx % CONVD);
    size_t bl = idx / CONVD;
    int l = (int)(bl % SEQLENN);
    int b = (int)(bl / SEQLENN);
    float acc = cb[c];
#pragma unroll
    for (int k = 0; k < DCONVN; k++) {
        int lt = l - (DCONVN - 1) + k;
        if (lt >= 0)
            acc = fmaf(cw[c * DCONVN + k],
                       g_zxbcdt[(size_t)(b * SEQLENN + lt) * DPROJ + DINNER + c], acc);
    }
    float sg = 1.f / (1.f + expf(-acc));
    g_xBCc[idx] = acc * sg;
}

// ------------------------- pass 1: per-segment local scan (STS-reduce) -------------------------
__global__ __launch_bounds__(256) void scan_seg_kernel(const float* __restrict__ A_log)
{
    const int bid = blockIdx.x;
    const int seg = bid & (NSEG - 1);
    const int h   = (bid >> 4) & (NHEADSN - 1);
    const int b   = bid >> 9;
    const int tid = threadIdx.x;
    const int p   = tid >> 2;
    const int sub = tid & 3;
    const float Ah = -expf(A_log[h]);
    const int bh = b * NHEADSN + h;
    const int rbase = b * SEQLENN + seg * SEGL;

    __shared__ __align__(16) float s_x[SCH][64];
    __shared__ __align__(16) float s_B[SCH][64];
    __shared__ __align__(16) float s_C[SCH][64];
    __shared__ __align__(16) float s_yp[SCH][256];
    __shared__ float s_dt[SCH];
    __shared__ float s_dA[SCH];
    __shared__ float s_ac[SCH];
    __shared__ float s_run;

    if (tid == 0) s_run = 1.f;

    float hreg[16];
#pragma unroll
    for (int j = 0; j < 16; j++) hreg[j] = 0.f;

    for (int t0 = 0; t0 < SEGL; t0 += SCH) {
        {
            int t = tid >> 4;
            int q = (tid & 15) << 2;
            size_t ro = (size_t)(rbase + t0 + t) * CONVD;
            *(float4*)&s_x[t][q] = *(const float4*)(g_xBCc + ro + h * 64 + q);
            *(float4*)&s_B[t][q] = *(const float4*)(g_xBCc + ro + DINNER + q);
            *(float4*)&s_C[t][q] = *(const float4*)(g_xBCc + ro + DINNER + DSTATE + q);
        }
        if (tid < SCH) {
            float dtv = g_dt[(size_t)(rbase + t0 + tid) * NHEADSN + h];
            s_dt[tid] = dtv;
            s_dA[tid] = expf(dtv * Ah);
        }
        __syncthreads();
        if (tid == 0) {
            float run = s_run;
#pragma unroll
            for (int t = 0; t < SCH; t++) { run *= s_dA[t]; s_ac[t] = run; }
            s_run = run;
        }
#pragma unroll 2
        for (int t = 0; t < SCH; t++) {
            float dA = s_dA[t];
            float dtx = s_dt[t] * s_x[t][p];
            const float4* Bq = (const float4*)&s_B[t][sub * 16];
            const float4* Cq = (const float4*)&s_C[t][sub * 16];
            float y0 = 0.f, y1 = 0.f, y2 = 0.f, y3 = 0.f;
            {
                float4 Bv = Bq[0], Cv = Cq[0];
                hreg[0] = fmaf(hreg[0], dA, dtx * Bv.x); y0 = fmaf(hreg[0], Cv.x, y0);
                hreg[1] = fmaf(hreg[1], dA, dtx * Bv.y); y1 = fmaf(hreg[1], Cv.y, y1);
                hreg[2] = fmaf(hreg[2], dA, dtx * Bv.z); y2 = fmaf(hreg[2], Cv.z, y2);
                hreg[3] = fmaf(hreg[3], dA, dtx * Bv.w); y3 = fmaf(hreg[3], Cv.w, y3);
            }
            {
                float4 Bv = Bq[1], Cv = Cq[1];
                hreg[4] = fmaf(hreg[4], dA, dtx * Bv.x); y0 = fmaf(hreg[4], Cv.x, y0);
                hreg[5] = fmaf(hreg[5], dA, dtx * Bv.y); y1 = fmaf(hreg[5], Cv.y, y1);
                hreg[6] = fmaf(hreg[6], dA, dtx * Bv.z); y2 = fmaf(hreg[6], Cv.z, y2);
                hreg[7] = fmaf(hreg[7], dA, dtx * Bv.w); y3 = fmaf(hreg[7], Cv.w, y3);
            }
            {
                float4 Bv = Bq[2], Cv = Cq[2];
                hreg[8]  = fmaf(hreg[8],  dA, dtx * Bv.x); y0 = fmaf(hreg[8],  Cv.x, y0);
                hreg[9]  = fmaf(hreg[9],  dA, dtx * Bv.y); y1 = fmaf(hreg[9],  Cv.y, y1);
                hreg[10] = fmaf(hreg[10], dA, dtx * Bv.z); y2 = fmaf(hreg[10], Cv.z, y2);
                hreg[11] = fmaf(hreg[11], dA, dtx * Bv.w); y3 = fmaf(hreg[11], Cv.w, y3);
            }
            {
                float4 Bv = Bq[3], Cv = Cq[3];
                hreg[12] = fmaf(hreg[12], dA, dtx * Bv.x); y0 = fmaf(hreg[12], Cv.x, y0);
                hreg[13] = fmaf(hreg[13], dA, dtx * Bv.y); y1 = fmaf(hreg[13], Cv.y, y1);
                hreg[14] = fmaf(hreg[14], dA, dtx * Bv.z); y2 = fmaf(hreg[14], Cv.z, y2);
                hreg[15] = fmaf(hreg[15], dA, dtx * Bv.w); y3 = fmaf(hreg[15], Cv.w, y3);
            }
            s_yp[t][tid] = (y0 + y1) + (y2 + y3);
        }
        __syncthreads();
#pragma unroll
        for (int it = 0; it < 4; it++) {
            int i = tid + it * 256;
            int tt = i >> 6, pp = i & 63;
            float4 v = *(float4*)&s_yp[tt][pp * 4];
            g_y[(size_t)(rbase + t0 + tt) * DINNER + h * 64 + pp] = (v.x + v.y) + (v.z + v.w);
        }
        if (tid < SCH)
            g_acum[(size_t)bh * SEQLENN + seg * SEGL + t0 + tid] = s_ac[tid];
        __syncthreads();
    }

    float* st = g_state + ((size_t)bh * NSEG + seg) * (64 * DSTATE) + p * DSTATE + sub * 16;
#pragma unroll
    for (int q = 0; q < 4; q++)
        *(float4*)(st + q * 4) = make_float4(hreg[q*4+0], hreg[q*4+1], hreg[q*4+2], hreg[q*4+3]);
}

// ------------------------- pass 2: prefix over segment states -------------------------
__global__ __launch_bounds__(256) void state_combine_kernel()
{
    const int bh = blockIdx.x;
    const int tid = threadIdx.x;
    const size_t base = (size_t)bh * NSEG * (64 * DSTATE);
    float4 hin[4];
#pragma unroll
    for (int q = 0; q < 4; q++) hin[q] = make_float4(0.f, 0.f, 0.f, 0.f);

    for (int seg = 1; seg < NSEG; seg++) {
        float ap = g_acum[(size_t)bh * SEQLENN + seg * SEGL - 1];
        const float4* sl = (const float4*)(g_state + base + (size_t)(seg - 1) * (64 * DSTATE) + tid * 16);
        float4* ho = (float4*)(g_hin + base + (size_t)seg * (64 * DSTATE) + tid * 16);
#pragma unroll
        for (int q = 0; q < 4; q++) {
            float4 s = sl[q];
            hin[q].x = fmaf(hin[q].x, ap, s.x);
            hin[q].y = fmaf(hin[q].y, ap, s.y);
            hin[q].z = fmaf(hin[q].z, ap, s.z);
            hin[q].w = fmaf(hin[q].w, ap, s.w);
            ho[q] = hin[q];
        }
    }
}

// ------------------------- pass 3 (MMA): y += (C .* acum) @ H_in^T -------------------------
__global__ __launch_bounds__(256) void carry_mma_kernel()
{
    const int bid = blockIdx.x;
    const int seg = 1 + (bid % (NSEG - 1));
    const int bh  = bid / (NSEG - 1);
    const int h   = bh & (NHEADSN - 1);
    const int b   = bh >> 5;
    const int rbase = b * SEQLENN + seg * SEGL;

    const int tid  = threadIdx.x;
    const int lane = tid & 31;
    const int warp = tid >> 5;
    const int wm   = (warp >> 1) * 64;
    const int wn   = (warp & 1) * 32;
    const int grp  = lane >> 2;
    const int qid  = lane & 3;

    __shared__ uint32_t Ah[8][264];
    __shared__ uint32_t Al[8][264];
    __shared__ uint32_t Bh2[32][72];
    __shared__ uint32_t Bl2[32][72];

    {
        const float* hi = g_hin + ((size_t)bh * NSEG + seg) * (64 * DSTATE);
        for (int i = tid; i < 64 * 32; i += 256) {
            int p  = i >> 5;
            int kp = i & 31;
            float a0 = hi[p * DSTATE + kp * 2];
            float a1 = hi[p * DSTATE + kp * 2 + 1];
            float r0, r1;
            Bh2[kp][p] = pack_hi(a0, a1, r0, r1);
            Bl2[kp][p] = pack_lo(r0, r1);
        }
    }

    float acc[4][4][4];
#pragma unroll
    for (int i = 0; i < 4; i++)
#pragma unroll
        for (int j = 0; j < 4; j++)
#pragma unroll
            for (int e = 0; e < 4; e++) acc[i][j][e] = 0.f;

    for (int k0 = 0; k0 < DSTATE; k0 += 16) {
#pragma unroll
        for (int ld = 0; ld < 4; ld++) {
            int idx = tid + ld * 256;
            int r = idx >> 2;
            int kk = (idx & 3) << 2;
            float al2 = g_acum[(size_t)bh * SEQLENN + seg * SEGL + r];
            float4 v = *(const float4*)(g_xBCc + (size_t)(rbase + r) * CONVD + DINNER + DSTATE + k0 + kk);
            v.x *= al2; v.y *= al2; v.z *= al2; v.w *= al2;
            int spp = kk >> 1;
            float r0, r1, r2, r3;
            Ah[spp    ][r] = pack_hi(v.x, v.y, r0, r1);
            Ah[spp + 1][r] = pack_hi(v.z, v.w, r2, r3);
            Al[spp    ][r] = pack_lo(r0, r1);
            Al[spp + 1][r] = pack_lo(r2, r3);
        }
        __syncthreads();

        const int kb = k0 >> 1;
        uint32_t ah[4][4], al[4][4];
#pragma unroll
        for (int mf = 0; mf < 4; mf++) {
            int r0 = wm + mf * 16 + grp;
            ah[mf][0] = Ah[qid    ][r0];
            ah[mf][1] = Ah[qid    ][r0 + 8];
            ah[mf][2] = Ah[qid + 4][r0];
            ah[mf][3] = Ah[qid + 4][r0 + 8];
            al[mf][0] = Al[qid    ][r0];
            al[mf][1] = Al[qid    ][r0 + 8];
            al[mf][2] = Al[qid + 4][r0];
            al[mf][3] = Al[qid + 4][r0 + 8];
        }
        uint32_t bh_[4][2], bl_[4][2];
#pragma unroll
        for (int nf = 0; nf < 4; nf++) {
            int c0 = wn + nf * 8 + grp;
            bh_[nf][0] = Bh2[kb + qid    ][c0];
            bh_[nf][1] = Bh2[kb + qid + 4][c0];
            bl_[nf][0] = Bl2[kb + qid    ][c0];
            bl_[nf][1] = Bl2[kb + qid + 4][c0];
        }
#pragma unroll
        for (int mf = 0; mf < 4; mf++)
#pragma unroll
            for (int nf = 0; nf < 4; nf++) {
                MMA_BF16(acc[mf][nf], ah[mf], bh_[nf]);
                MMA_BF16(acc[mf][nf], ah[mf], bl_[nf]);
                MMA_BF16(acc[mf][nf], al[mf], bh_[nf]);
            }
        __syncthreads();
    }

#pragma unroll
    for (int mf = 0; mf < 4; mf++) {
        int t0 = wm + mf * 16 + grp;
        int t1 = t0 + 8;
#pragma unroll
        for (int nf = 0; nf < 4; nf++) {
            int gp = wn + nf * 8 + 2 * qid;
            size_t o0 = (size_t)(rbase + t0) * DINNER + h * 64 + gp;
            size_t o1 = (size_t)(rbase + t1) * DINNER + h * 64 + gp;
            g_y[o0]     += acc[mf][nf][0];
            g_y[o0 + 1] += acc[mf][nf][1];
            g_y[o1]     += acc[mf][nf][2];
            g_y[o1 + 1] += acc[mf][nf][3];
        }
    }
}

// ------------------------- D*x, gate, RMSNorm -> packed fp16 hi/lo -------------------------
__global__ __launch_bounds__(256) void gate_norm_kernel(
    const float* __restrict__ Dp, const float* __restrict__ norm_w)
{
    const int row = blockIdx.x;
    const int tid = threadIdx.x;
    const int c0 = tid * 8;
    const int hh = c0 >> 6;

    float vals[8];
    float ss = 0.f;
    {
        const float4* yv = (const float4*)(g_y + (size_t)row * DINNER + c0);
        const float4* xv = (const float4*)(g_xBCc + (size_t)row * CONVD + c0);
        const float4* zv = (const float4*)(g_zxbcdt + (size_t)row * DPROJ + c0);
        float Dh = Dp[hh];
#pragma unroll
        for (int q = 0; q < 2; q++) {
            float4 y = yv[q], x = xv[q], z = zv[q];
            float a[4] = {y.x, y.y, y.z, y.w};
            float b[4] = {x.x, x.y, x.z, x.w};
            float g[4] = {z.x, z.y, z.z, z.w};
#pragma unroll
            for (int e = 0; e < 4; e++) {
                float yy = fmaf(Dh, b[e], a[e]);
                float gg = g[e] / (1.f + expf(-g[e]));
                float v = yy * gg;
                vals[q * 4 + e] = v;
                ss = fmaf(v, v, ss);
            }
        }
    }
    __shared__ float red[32];
    for (int o = 16; o; o >>= 1) ss += __shfl_down_sync(0xffffffffu, ss, o);
    if ((tid & 31) == 0) red[tid >> 5] = ss;
    __syncthreads();
    if (tid < 32) {
        float s2 = (tid < 8) ? red[tid] : 0.f;
        for (int o = 4; o; o >>= 1) s2 += __shfl_down_sync(0xffffffffu, s2, o);
        if (tid == 0) red[0] = s2;
    }
    __syncthreads();
    float scale = rsqrtf(red[0] / (float)DINNER + EPSV);

    uint32_t ho[4], lo[4];
#pragma unroll
    for (int j = 0; j < 4; j++) {
        float a = vals[2*j]     * scale * norm_w[c0 + 2*j];
        float b = vals[2*j + 1] * scale * norm_w[c0 + 2*j + 1];
        float r0, r1;
        ho[j] = packh_hi(a, b, r0, r1);
        lo[j] = packh(r0, r1);
    }
    *(uint4*)(g_ynh + (size_t)row * (DINNER/2) + tid * 4) = *(uint4*)ho;
    *(uint4*)(g_ynl + (size_t)row * (DINNER/2) + tid * 4) = *(uint4*)lo;
}

// ------------------------- launch -------------------------
extern "C" void kernel_launch(void* const* d_in, const int* in_sizes, int n_in,
                              void* d_out, int out_size)
{
    const float* X          = (const float*)d_in[0];
    const float* in_proj_w  = (const float*)d_in[1];
    const float* conv_w     = (const float*)d_in[2];
    const float* conv_b     = (const float*)d_in[3];
    const float* dt_bias    = (const float*)d_in[4];
    const float* A_log      = (const float*)d_in[5];
    const float* Dp         = (const float*)d_in[6];
    const float* norm_w     = (const float*)d_in[7];
    const float* out_proj_w = (const float*)d_in[8];
    const float* to_h_w     = (const float*)d_in[9];
    float* out = (float*)d_out;

    float *zx;
    uint32_t *Woh, *Wth, *ynh, *ynl, *Hh, *Hl;
    cudaGetSymbolAddress((void**)&zx,  g_zxbcdt);
    cudaGetSymbolAddress((void**)&Woh, g_Woh);
    cudaGetSymbolAddress((void**)&Wth, g_Wth);
    cudaGetSymbolAddress((void**)&ynh, g_ynh); cudaGetSymbolAddress((void**)&ynl, g_ynl);
    cudaGetSymbolAddress((void**)&Hh,  g_Hh);  cudaGetSymbolAddress((void**)&Hl,  g_Hl);

    // 0) pack weights to fp16 (hi only)
    pack_f16_kernel<<<(DIMN * DINNER / 4 + 255) / 256, 256>>>(out_proj_w, Woh, DIMN * DINNER / 4);
    pack_f16_kernel<<<(DINNER * DIMN / 4 + 255) / 256, 256>>>(to_h_w, Wth, DINNER * DIMN / 4);

    // 1) zxbcdt = X @ in_proj_w^T  (bf16 3-split)
    gemm_nt_tc<<<dim3((DPROJ + 127) / 128, NROWS / 128), 256>>>(X, in_proj_w, zx, NROWS, DPROJ, DIMN);
    // 2) dt
    dt_kernel<<<(NROWS * NHEADSN + 255) / 256, 256>>>(dt_bias);
    // 3) conv + silu
    conv_silu_kernel<<<(int)(((size_t)NROWS * CONVD + 255) / 256), 256>>>(conv_w, conv_b);
    // 4) segmented scan
    scan_seg_kernel<<<BATCHN * NHEADSN * NSEG, 256>>>(A_log);
    state_combine_kernel<<<BATCHN * NHEADSN, 256>>>();
    carry_mma_kernel<<<BATCHN * NHEADSN * (NSEG - 1), 256>>>();
    // 5) gate + rmsnorm -> packed fp16 yn
    gate_norm_kernel<<<NROWS, 256>>>(Dp, norm_w);
    // 6) H = yn @ out_proj_w^T  (fp16 2-MMA, packed out)
    gemm_f16<1><<<dim3(DIMN / 128, NROWS / 128), 256>>>(
        ynh, ynl, Woh, nullptr, Hh, Hl, NROWS, DIMN, DINNER);
    // 7) HKV = H @ to_h_w^T with fused split  (fp16 2-MMA)
    gemm_f16<2><<<dim3(DINNER / 128, NROWS / 128), 256>>>(
        Hh, Hl, Wth, out, nullptr, nullptr, NROWS, DINNER, DIMN);
}

// round 9
// speedup vs baseline: 1.1842x; 1.0580x over previous
#include <cuda_runtime.h>
#include <cuda_bf16.h>
#include <cuda_fp16.h>
#include <math.h>
#include <stdint.h>

#define BATCHN 2
#define SEQLENN 4096
#define DIMN 1024
#define DSTATE 64
#define DCONVN 4
#define DINNER 2048
#define NHEADSN 32
#define CONVD 2176          // D_INNER + 2*D_STATE
#define ZXW 4224            // z + xBC columns (dt handled separately); 33*128
#define NROWS (BATCHN*SEQLENN)   // 8192
#define NSEG 16
#define SEGL (SEQLENN/NSEG) // 256
#define SCH 16
#define EPSV 1e-5f

// ------------------------- scratch -------------------------
__device__ float g_zxbcdt[(size_t)NROWS * ZXW];     // z | xBC (fp16-GEMM output)
__device__ float g_xBCc[(size_t)NROWS * CONVD];
__device__ float g_dt[(size_t)NROWS * NHEADSN];
__device__ float g_y[(size_t)NROWS * DINNER];
__device__ float g_state[(size_t)BATCHN * NHEADSN * NSEG * DSTATE * 64];
__device__ float g_hin[(size_t)BATCHN * NHEADSN * NSEG * DSTATE * 64];
__device__ float g_acum[(size_t)BATCHN * NHEADSN * SEQLENN];

// packed fp16 operands (uint32 = 2 halves along K)
__device__ uint32_t g_Xh[(size_t)NROWS * (DIMN/2)], g_Xl[(size_t)NROWS * (DIMN/2)];
__device__ uint32_t g_Wih[(size_t)ZXW * (DIMN/2)];
__device__ uint32_t g_Woh[(size_t)DIMN * (DINNER/2)];
__device__ uint32_t g_Wth[(size_t)DINNER * (DIMN/2)];
__device__ uint32_t g_ynh[(size_t)NROWS * (DINNER/2)], g_ynl[(size_t)NROWS * (DINNER/2)];
__device__ uint32_t g_Hh[(size_t)NROWS * (DIMN/2)],    g_Hl[(size_t)NROWS * (DIMN/2)];

// ------------------------- bf16 helpers (carry MMA) -------------------------
__device__ __forceinline__ uint32_t pack_hi(float a, float b, float& ra, float& rb) {
    __nv_bfloat162 h = __floats2bfloat162_rn(a, b);
    ra = a - __bfloat162float(h.x);
    rb = b - __bfloat162float(h.y);
    return *(uint32_t*)&h;
}
__device__ __forceinline__ uint32_t pack_lo(float a, float b) {
    __nv_bfloat162 h = __floats2bfloat162_rn(a, b);
    return *(uint32_t*)&h;
}
// fp16 helpers
__device__ __forceinline__ uint32_t packh_hi(float a, float b, float& ra, float& rb) {
    __half2 h = __floats2half2_rn(a, b);
    ra = a - __half2float(__low2half(h));
    rb = b - __half2float(__high2half(h));
    return *(uint32_t*)&h;
}
__device__ __forceinline__ uint32_t packh(float a, float b) {
    __half2 h = __floats2half2_rn(a, b);
    return *(uint32_t*)&h;
}

#define MMA_BF16(c, a, b) \
    asm volatile("mma.sync.aligned.m16n8k16.row.col.f32.bf16.bf16.f32 " \
        "{%0,%1,%2,%3}, {%4,%5,%6,%7}, {%8,%9}, {%0,%1,%2,%3};" \
        : "+f"((c)[0]), "+f"((c)[1]), "+f"((c)[2]), "+f"((c)[3]) \
        : "r"((a)[0]), "r"((a)[1]), "r"((a)[2]), "r"((a)[3]), \
          "r"((b)[0]), "r"((b)[1]))

#define MMA_F16(c, a, b) \
    asm volatile("mma.sync.aligned.m16n8k16.row.col.f32.f16.f16.f32 " \
        "{%0,%1,%2,%3}, {%4,%5,%6,%7}, {%8,%9}, {%0,%1,%2,%3};" \
        : "+f"((c)[0]), "+f"((c)[1]), "+f"((c)[2]), "+f"((c)[3]) \
        : "r"((a)[0]), "r"((a)[1]), "r"((a)[2]), "r"((a)[3]), \
          "r"((b)[0]), "r"((b)[1]))

// ------------------------- fp16 2-MMA GEMM: C[M,N] = (Ah+Al)[M,K] @ Bh[N,K]^T -------------------------
// MODE 0: f32 C (N exact multiple of 128).  MODE 1: packed fp16 hi/lo C.  MODE 2: f32 out with HK|HV split.
template<int MODE>
__global__ __launch_bounds__(256) void gemm_f16(
    const uint32_t* __restrict__ Ahg, const uint32_t* __restrict__ Alg,
    const uint32_t* __restrict__ Bhg,
    float* __restrict__ Cf, uint32_t* __restrict__ Ch, uint32_t* __restrict__ Cl,
    int M, int N, int K)
{
    __shared__ uint32_t Ah[8][136];
    __shared__ uint32_t Al[8][136];
    __shared__ uint32_t Bh[8][136];

    const int tid  = threadIdx.x;
    const int bm   = blockIdx.y * 128;
    const int bn   = blockIdx.x * 128;
    const int lane = tid & 31;
    const int warp = tid >> 5;
    const int wm   = (warp >> 2) * 64;
    const int wn   = (warp & 3) * 32;
    const int grp  = lane >> 2;
    const int qid  = lane & 3;
    const int K2   = K >> 1;

    const int sr = tid >> 1;          // 0..127
    const int sc = (tid & 1) * 4;     // 0 or 4
    const size_t aoff = (size_t)(bm + sr) * K2 + sc;
    const size_t boff = (size_t)(bn + sr) * K2 + sc;

    float acc[4][4][4];
#pragma unroll
    for (int i = 0; i < 4; i++)
#pragma unroll
        for (int j = 0; j < 4; j++)
#pragma unroll
            for (int e = 0; e < 4; e++) acc[i][j][e] = 0.f;

    uint4 avh = *(const uint4*)(Ahg + aoff);
    uint4 avl = *(const uint4*)(Alg + aoff);
    uint4 bvh = *(const uint4*)(Bhg + boff);

    for (int kb = 0; kb < K2; kb += 8) {
        Ah[sc + 0][sr] = avh.x; Ah[sc + 1][sr] = avh.y;
        Ah[sc + 2][sr] = avh.z; Ah[sc + 3][sr] = avh.w;
        Al[sc + 0][sr] = avl.x; Al[sc + 1][sr] = avl.y;
        Al[sc + 2][sr] = avl.z; Al[sc + 3][sr] = avl.w;
        Bh[sc + 0][sr] = bvh.x; Bh[sc + 1][sr] = bvh.y;
        Bh[sc + 2][sr] = bvh.z; Bh[sc + 3][sr] = bvh.w;
        __syncthreads();

        if (kb + 8 < K2) {
            avh = *(const uint4*)(Ahg + aoff + kb + 8);
            avl = *(const uint4*)(Alg + aoff + kb + 8);
            bvh = *(const uint4*)(Bhg + boff + kb + 8);
        }

        uint32_t ah[4][4], al[4][4];
#pragma unroll
        for (int mf = 0; mf < 4; mf++) {
            int r0 = wm + mf * 16 + grp;
            ah[mf][0] = Ah[qid    ][r0];
            ah[mf][1] = Ah[qid    ][r0 + 8];
            ah[mf][2] = Ah[qid + 4][r0];
            ah[mf][3] = Ah[qid + 4][r0 + 8];
            al[mf][0] = Al[qid    ][r0];
            al[mf][1] = Al[qid    ][r0 + 8];
            al[mf][2] = Al[qid + 4][r0];
            al[mf][3] = Al[qid + 4][r0 + 8];
        }
        uint32_t bh[4][2];
#pragma unroll
        for (int nf = 0; nf < 4; nf++) {
            int c0 = wn + nf * 8 + grp;
            bh[nf][0] = Bh[qid    ][c0];
            bh[nf][1] = Bh[qid + 4][c0];
        }
#pragma unroll
        for (int mf = 0; mf < 4; mf++)
#pragma unroll
            for (int nf = 0; nf < 4; nf++) {
                MMA_F16(acc[mf][nf], ah[mf], bh[nf]);
                MMA_F16(acc[mf][nf], al[mf], bh[nf]);
            }
        __syncthreads();
    }

#pragma unroll
    for (int mf = 0; mf < 4; mf++) {
        int gr0 = bm + wm + mf * 16 + grp;
        int gr1 = gr0 + 8;
#pragma unroll
        for (int nf = 0; nf < 4; nf++) {
            int gc = bn + wn + nf * 8 + 2 * qid;
            if (MODE == 0) {
                Cf[(size_t)gr0 * N + gc]     = acc[mf][nf][0];
                Cf[(size_t)gr0 * N + gc + 1] = acc[mf][nf][1];
                Cf[(size_t)gr1 * N + gc]     = acc[mf][nf][2];
                Cf[(size_t)gr1 * N + gc + 1] = acc[mf][nf][3];
            } else if (MODE == 1) {
                int kp = gc >> 1;
                float r0, r1;
                Ch[(size_t)gr0 * (N/2) + kp] = packh_hi(acc[mf][nf][0], acc[mf][nf][1], r0, r1);
                Cl[(size_t)gr0 * (N/2) + kp] = packh(r0, r1);
                Ch[(size_t)gr1 * (N/2) + kp] = packh_hi(acc[mf][nf][2], acc[mf][nf][3], r0, r1);
                Cl[(size_t)gr1 * (N/2) + kp] = packh(r0, r1);
            } else {
                size_t off = (gc < DIMN)
                    ? (size_t)gr0 * DIMN + gc
                    : (size_t)NROWS * DIMN + (size_t)gr0 * DIMN + (gc - DIMN);
                Cf[off]     = acc[mf][nf][0];
                Cf[off + 1] = acc[mf][nf][1];
                size_t off1 = off + (size_t)8 * DIMN;
                Cf[off1]     = acc[mf][nf][2];
                Cf[off1 + 1] = acc[mf][nf][3];
            }
        }
    }
}

// ------------------------- pack kernels -------------------------
__global__ void pack_f16_kernel(const float* __restrict__ src, uint32_t* __restrict__ hi, int n4)
{
    int i = blockIdx.x * blockDim.x + threadIdx.x;
    if (i >= n4) return;
    float4 v = ((const float4*)src)[i];
    ((uint2*)hi)[i] = make_uint2(packh(v.x, v.y), packh(v.z, v.w));
}
__global__ void pack_f16hl_kernel(const float* __restrict__ src,
                                  uint32_t* __restrict__ hi, uint32_t* __restrict__ lo, int n4)
{
    int i = blockIdx.x * blockDim.x + threadIdx.x;
    if (i >= n4) return;
    float4 v = ((const float4*)src)[i];
    float r0, r1, r2, r3;
    uint32_t h0 = packh_hi(v.x, v.y, r0, r1);
    uint32_t h1 = packh_hi(v.z, v.w, r2, r3);
    ((uint2*)hi)[i] = make_uint2(h0, h1);
    ((uint2*)lo)[i] = make_uint2(packh(r0, r1), packh(r2, r3));
}

// ------------------------- dt GEMV (fp32 exact) + softplus -------------------------
// dt_raw[row][h] = X[row] . in_proj_w[ZXW + h]; one block per row.
__global__ __launch_bounds__(256) void dt_gemv_kernel(
    const float* __restrict__ X, const float* __restrict__ Wi, const float* __restrict__ dt_bias)
{
    const int row  = blockIdx.x;
    const int tid  = threadIdx.x;
    const int warp = tid >> 5;
    const int lane = tid & 31;
    __shared__ __align__(16) float sx[DIMN];
    *(float4*)&sx[tid * 4] = *(const float4*)(X + (size_t)row * DIMN + tid * 4);
    __syncthreads();
#pragma unroll
    for (int hh = 0; hh < 4; hh++) {
        int h = warp * 4 + hh;
        const float* w = Wi + (size_t)(ZXW + h) * DIMN;
        float s = 0.f;
#pragma unroll
        for (int i = 0; i < 8; i++) {
            int k = (lane + i * 32) * 4;
            float4 xv = *(const float4*)&sx[k];
            float4 wv = *(const float4*)(w + k);
            s = fmaf(xv.x, wv.x, s); s = fmaf(xv.y, wv.y, s);
            s = fmaf(xv.z, wv.z, s); s = fmaf(xv.w, wv.w, s);
        }
        for (int o = 16; o; o >>= 1) s += __shfl_down_sync(0xffffffffu, s, o);
        if (lane == 0) {
            float v = s + dt_bias[h];
            g_dt[(size_t)row * NHEADSN + h] = (v > 20.f) ? v : log1pf(expf(v));
        }
    }
}

// ------------------------- depthwise causal conv (w=4) + bias + SiLU -------------------------
__global__ void conv_silu_kernel(const float* __restrict__ cw, const float* __restrict__ cb)
{
    size_t idx = (size_t)blockIdx.x * blockDim.x + threadIdx.x;
    if (idx >= (size_t)NROWS * CONVD) return;
    int c = (int)(idx % CONVD);
    size_t bl = idx / CONVD;
    int l = (int)(bl % SEQLENN);
    int b = (int)(bl / SEQLENN);
    float acc = cb[c];
#pragma unroll
    for (int k = 0; k < DCONVN; k++) {
        int lt = l - (DCONVN - 1) + k;
        if (lt >= 0)
            acc = fmaf(cw[c * DCONVN + k],
                       g_zxbcdt[(size_t)(b * SEQLENN + lt) * ZXW + DINNER + c], acc);
    }
    float sg = 1.f / (1.f + expf(-acc));
    g_xBCc[idx] = acc * sg;
}

// ------------------------- pass 1: per-segment local scan (STS-reduce) -------------------------
__global__ __launch_bounds__(256) void scan_seg_kernel(const float* __restrict__ A_log)
{
    const int bid = blockIdx.x;
    const int seg = bid & (NSEG - 1);
    const int h   = (bid >> 4) & (NHEADSN - 1);
    const int b   = bid >> 9;
    const int tid = threadIdx.x;
    const int p   = tid >> 2;
    const int sub = tid & 3;
    const float Ah = -expf(A_log[h]);
    const int bh = b * NHEADSN + h;
    const int rbase = b * SEQLENN + seg * SEGL;

    __shared__ __align__(16) float s_x[SCH][64];
    __shared__ __align__(16) float s_B[SCH][64];
    __shared__ __align__(16) float s_C[SCH][64];
    __shared__ __align__(16) float s_yp[SCH][256];
    __shared__ float s_dt[SCH];
    __shared__ float s_dA[SCH];
    __shared__ float s_ac[SCH];
    __shared__ float s_run;

    if (tid == 0) s_run = 1.f;

    float hreg[16];
#pragma unroll
    for (int j = 0; j < 16; j++) hreg[j] = 0.f;

    for (int t0 = 0; t0 < SEGL; t0 += SCH) {
        {
            int t = tid >> 4;
            int q = (tid & 15) << 2;
            size_t ro = (size_t)(rbase + t0 + t) * CONVD;
            *(float4*)&s_x[t][q] = *(const float4*)(g_xBCc + ro + h * 64 + q);
            *(float4*)&s_B[t][q] = *(const float4*)(g_xBCc + ro + DINNER + q);
            *(float4*)&s_C[t][q] = *(const float4*)(g_xBCc + ro + DINNER + DSTATE + q);
        }
        if (tid < SCH) {
            float dtv = g_dt[(size_t)(rbase + t0 + tid) * NHEADSN + h];
            s_dt[tid] = dtv;
            s_dA[tid] = expf(dtv * Ah);
        }
        __syncthreads();
        if (tid == 0) {
            float run = s_run;
#pragma unroll
            for (int t = 0; t < SCH; t++) { run *= s_dA[t]; s_ac[t] = run; }
            s_run = run;
        }
#pragma unroll 2
        for (int t = 0; t < SCH; t++) {
            float dA = s_dA[t];
            float dtx = s_dt[t] * s_x[t][p];
            const float4* Bq = (const float4*)&s_B[t][sub * 16];
            const float4* Cq = (const float4*)&s_C[t][sub * 16];
            float y0 = 0.f, y1 = 0.f, y2 = 0.f, y3 = 0.f;
            {
                float4 Bv = Bq[0], Cv = Cq[0];
                hreg[0] = fmaf(hreg[0], dA, dtx * Bv.x); y0 = fmaf(hreg[0], Cv.x, y0);
                hreg[1] = fmaf(hreg[1], dA, dtx * Bv.y); y1 = fmaf(hreg[1], Cv.y, y1);
                hreg[2] = fmaf(hreg[2], dA, dtx * Bv.z); y2 = fmaf(hreg[2], Cv.z, y2);
                hreg[3] = fmaf(hreg[3], dA, dtx * Bv.w); y3 = fmaf(hreg[3], Cv.w, y3);
            }
            {
                float4 Bv = Bq[1], Cv = Cq[1];
                hreg[4] = fmaf(hreg[4], dA, dtx * Bv.x); y0 = fmaf(hreg[4], Cv.x, y0);
                hreg[5] = fmaf(hreg[5], dA, dtx * Bv.y); y1 = fmaf(hreg[5], Cv.y, y1);
                hreg[6] = fmaf(hreg[6], dA, dtx * Bv.z); y2 = fmaf(hreg[6], Cv.z, y2);
                hreg[7] = fmaf(hreg[7], dA, dtx * Bv.w); y3 = fmaf(hreg[7], Cv.w, y3);
            }
            {
                float4 Bv = Bq[2], Cv = Cq[2];
                hreg[8]  = fmaf(hreg[8],  dA, dtx * Bv.x); y0 = fmaf(hreg[8],  Cv.x, y0);
                hreg[9]  = fmaf(hreg[9],  dA, dtx * Bv.y); y1 = fmaf(hreg[9],  Cv.y, y1);
                hreg[10] = fmaf(hreg[10], dA, dtx * Bv.z); y2 = fmaf(hreg[10], Cv.z, y2);
                hreg[11] = fmaf(hreg[11], dA, dtx * Bv.w); y3 = fmaf(hreg[11], Cv.w, y3);
            }
            {
                float4 Bv = Bq[3], Cv = Cq[3];
                hreg[12] = fmaf(hreg[12], dA, dtx * Bv.x); y0 = fmaf(hreg[12], Cv.x, y0);
                hreg[13] = fmaf(hreg[13], dA, dtx * Bv.y); y1 = fmaf(hreg[13], Cv.y, y1);
                hreg[14] = fmaf(hreg[14], dA, dtx * Bv.z); y2 = fmaf(hreg[14], Cv.z, y2);
                hreg[15] = fmaf(hreg[15], dA, dtx * Bv.w); y3 = fmaf(hreg[15], Cv.w, y3);
            }
            s_yp[t][tid] = (y0 + y1) + (y2 + y3);
        }
        __syncthreads();
#pragma unroll
        for (int it = 0; it < 4; it++) {
            int i = tid + it * 256;
            int tt = i >> 6, pp = i & 63;
            float4 v = *(float4*)&s_yp[tt][pp * 4];
            g_y[(size_t)(rbase + t0 + tt) * DINNER + h * 64 + pp] = (v.x + v.y) + (v.z + v.w);
        }
        if (tid < SCH)
            g_acum[(size_t)bh * SEQLENN + seg * SEGL + t0 + tid] = s_ac[tid];
        __syncthreads();
    }

    float* st = g_state + ((size_t)bh * NSEG + seg) * (64 * DSTATE) + p * DSTATE + sub * 16;
#pragma unroll
    for (int q = 0; q < 4; q++)
        *(float4*)(st + q * 4) = make_float4(hreg[q*4+0], hreg[q*4+1], hreg[q*4+2], hreg[q*4+3]);
}

// ------------------------- pass 2: prefix over segment states -------------------------
__global__ __launch_bounds__(256) void state_combine_kernel()
{
    const int bh = blockIdx.x;
    const int tid = threadIdx.x;
    const size_t base = (size_t)bh * NSEG * (64 * DSTATE);
    float4 hin[4];
#pragma unroll
    for (int q = 0; q < 4; q++) hin[q] = make_float4(0.f, 0.f, 0.f, 0.f);

    for (int seg = 1; seg < NSEG; seg++) {
        float ap = g_acum[(size_t)bh * SEQLENN + seg * SEGL - 1];
        const float4* sl = (const float4*)(g_state + base + (size_t)(seg - 1) * (64 * DSTATE) + tid * 16);
        float4* ho = (float4*)(g_hin + base + (size_t)seg * (64 * DSTATE) + tid * 16);
#pragma unroll
        for (int q = 0; q < 4; q++) {
            float4 s = sl[q];
            hin[q].x = fmaf(hin[q].x, ap, s.x);
            hin[q].y = fmaf(hin[q].y, ap, s.y);
            hin[q].z = fmaf(hin[q].z, ap, s.z);
            hin[q].w = fmaf(hin[q].w, ap, s.w);
            ho[q] = hin[q];
        }
    }
}

// ------------------------- pass 3 (MMA): y += (C .* acum) @ H_in^T -------------------------
__global__ __launch_bounds__(256) void carry_mma_kernel()
{
    const int bid = blockIdx.x;
    const int seg = 1 + (bid % (NSEG - 1));
    const int bh  = bid / (NSEG - 1);
    const int h   = bh & (NHEADSN - 1);
    const int b   = bh >> 5;
    const int rbase = b * SEQLENN + seg * SEGL;

    const int tid  = threadIdx.x;
    const int lane = tid & 31;
    const int warp = tid >> 5;
    const int wm   = (warp >> 1) * 64;
    const int wn   = (warp & 1) * 32;
    const int grp  = lane >> 2;
    const int qid  = lane & 3;

    __shared__ uint32_t Ah[8][264];
    __shared__ uint32_t Al[8][264];
    __shared__ uint32_t Bh2[32][72];
    __shared__ uint32_t Bl2[32][72];

    {
        const float* hi = g_hin + ((size_t)bh * NSEG + seg) * (64 * DSTATE);
        for (int i = tid; i < 64 * 32; i += 256) {
            int p  = i >> 5;
            int kp = i & 31;
            float a0 = hi[p * DSTATE + kp * 2];
            float a1 = hi[p * DSTATE + kp * 2 + 1];
            float r0, r1;
            Bh2[kp][p] = pack_hi(a0, a1, r0, r1);
            Bl2[kp][p] = pack_lo(r0, r1);
        }
    }

    float acc[4][4][4];
#pragma unroll
    for (int i = 0; i < 4; i++)
#pragma unroll
        for (int j = 0; j < 4; j++)
#pragma unroll
            for (int e = 0; e < 4; e++) acc[i][j][e] = 0.f;

    for (int k0 = 0; k0 < DSTATE; k0 += 16) {
#pragma unroll
        for (int ld = 0; ld < 4; ld++) {
            int idx = tid + ld * 256;
            int r = idx >> 2;
            int kk = (idx & 3) << 2;
            float al2 = g_acum[(size_t)bh * SEQLENN + seg * SEGL + r];
            float4 v = *(const float4*)(g_xBCc + (size_t)(rbase + r) * CONVD + DINNER + DSTATE + k0 + kk);
            v.x *= al2; v.y *= al2; v.z *= al2; v.w *= al2;
            int spp = kk >> 1;
            float r0, r1, r2, r3;
            Ah[spp    ][r] = pack_hi(v.x, v.y, r0, r1);
            Ah[spp + 1][r] = pack_hi(v.z, v.w, r2, r3);
            Al[spp    ][r] = pack_lo(r0, r1);
            Al[spp + 1][r] = pack_lo(r2, r3);
        }
        __syncthreads();

        const int kb = k0 >> 1;
        uint32_t ah[4][4], al[4][4];
#pragma unroll
        for (int mf = 0; mf < 4; mf++) {
            int r0 = wm + mf * 16 + grp;
            ah[mf][0] = Ah[qid    ][r0];
            ah[mf][1] = Ah[qid    ][r0 + 8];
            ah[mf][2] = Ah[qid + 4][r0];
            ah[mf][3] = Ah[qid + 4][r0 + 8];
            al[mf][0] = Al[qid    ][r0];
            al[mf][1] = Al[qid    ][r0 + 8];
            al[mf][2] = Al[qid + 4][r0];
            al[mf][3] = Al[qid + 4][r0 + 8];
        }
        uint32_t bh_[4][2], bl_[4][2];
#pragma unroll
        for (int nf = 0; nf < 4; nf++) {
            int c0 = wn + nf * 8 + grp;
            bh_[nf][0] = Bh2[kb + qid    ][c0];
            bh_[nf][1] = Bh2[kb + qid + 4][c0];
            bl_[nf][0] = Bl2[kb + qid    ][c0];
            bl_[nf][1] = Bl2[kb + qid + 4][c0];
        }
#pragma unroll
        for (int mf = 0; mf < 4; mf++)
#pragma unroll
            for (int nf = 0; nf < 4; nf++) {
                MMA_BF16(acc[mf][nf], ah[mf], bh_[nf]);
                MMA_BF16(acc[mf][nf], ah[mf], bl_[nf]);
                MMA_BF16(acc[mf][nf], al[mf], bh_[nf]);
            }
        __syncthreads();
    }

#pragma unroll
    for (int mf = 0; mf < 4; mf++) {
        int t0 = wm + mf * 16 + grp;
        int t1 = t0 + 8;
#pragma unroll
        for (int nf = 0; nf < 4; nf++) {
            int gp = wn + nf * 8 + 2 * qid;
            size_t o0 = (size_t)(rbase + t0) * DINNER + h * 64 + gp;
            size_t o1 = (size_t)(rbase + t1) * DINNER + h * 64 + gp;
            g_y[o0]     += acc[mf][nf][0];
            g_y[o0 + 1] += acc[mf][nf][1];
            g_y[o1]     += acc[mf][nf][2];
            g_y[o1 + 1] += acc[mf][nf][3];
        }
    }
}

// ------------------------- D*x, gate, RMSNorm -> packed fp16 hi/lo -------------------------
__global__ __launch_bounds__(256) void gate_norm_kernel(
    const float* __restrict__ Dp, const float* __restrict__ norm_w)
{
    const int row = blockIdx.x;
    const int tid = threadIdx.x;
    const int c0 = tid * 8;
    const int hh = c0 >> 6;

    float vals[8];
    float ss = 0.f;
    {
        const float4* yv = (const float4*)(g_y + (size_t)row * DINNER + c0);
        const float4* xv = (const float4*)(g_xBCc + (size_t)row * CONVD + c0);
        const float4* zv = (const float4*)(g_zxbcdt + (size_t)row * ZXW + c0);
        float Dh = Dp[hh];
#pragma unroll
        for (int q = 0; q < 2; q++) {
            float4 y = yv[q], x = xv[q], z = zv[q];
            float a[4] = {y.x, y.y, y.z, y.w};
            float b[4] = {x.x, x.y, x.z, x.w};
            float g[4] = {z.x, z.y, z.z, z.w};
#pragma unroll
            for (int e = 0; e < 4; e++) {
                float yy = fmaf(Dh, b[e], a[e]);
                float gg = g[e] / (1.f + expf(-g[e]));
                float v = yy * gg;
                vals[q * 4 + e] = v;
                ss = fmaf(v, v, ss);
            }
        }
    }
    __shared__ float red[32];
    for (int o = 16; o; o >>= 1) ss += __shfl_down_sync(0xffffffffu, ss, o);
    if ((tid & 31) == 0) red[tid >> 5] = ss;
    __syncthreads();
    if (tid < 32) {
        float s2 = (tid < 8) ? red[tid] : 0.f;
        for (int o = 4; o; o >>= 1) s2 += __shfl_down_sync(0xffffffffu, s2, o);
        if (tid == 0) red[0] = s2;
    }
    __syncthreads();
    float scale = rsqrtf(red[0] / (float)DINNER + EPSV);

    uint32_t ho[4], lo[4];
#pragma unroll
    for (int j = 0; j < 4; j++) {
        float a = vals[2*j]     * scale * norm_w[c0 + 2*j];
        float b = vals[2*j + 1] * scale * norm_w[c0 + 2*j + 1];
        float r0, r1;
        ho[j] = packh_hi(a, b, r0, r1);
        lo[j] = packh(r0, r1);
    }
    *(uint4*)(g_ynh + (size_t)row * (DINNER/2) + tid * 4) = *(uint4*)ho;
    *(uint4*)(g_ynl + (size_t)row * (DINNER/2) + tid * 4) = *(uint4*)lo;
}

// ------------------------- launch -------------------------
extern "C" void kernel_launch(void* const* d_in, const int* in_sizes, int n_in,
                              void* d_out, int out_size)
{
    const float* X          = (const float*)d_in[0];
    const float* in_proj_w  = (const float*)d_in[1];
    const float* conv_w     = (const float*)d_in[2];
    const float* conv_b     = (const float*)d_in[3];
    const float* dt_bias    = (const float*)d_in[4];
    const float* A_log      = (const float*)d_in[5];
    const float* Dp         = (const float*)d_in[6];
    const float* norm_w     = (const float*)d_in[7];
    const float* out_proj_w = (const float*)d_in[8];
    const float* to_h_w     = (const float*)d_in[9];
    float* out = (float*)d_out;

    float *zx;
    uint32_t *Xh, *Xl, *Wih, *Woh, *Wth, *ynh, *ynl, *Hh, *Hl;
    cudaGetSymbolAddress((void**)&zx,  g_zxbcdt);
    cudaGetSymbolAddress((void**)&Xh,  g_Xh);  cudaGetSymbolAddress((void**)&Xl,  g_Xl);
    cudaGetSymbolAddress((void**)&Wih, g_Wih);
    cudaGetSymbolAddress((void**)&Woh, g_Woh);
    cudaGetSymbolAddress((void**)&Wth, g_Wth);
    cudaGetSymbolAddress((void**)&ynh, g_ynh); cudaGetSymbolAddress((void**)&ynl, g_ynl);
    cudaGetSymbolAddress((void**)&Hh,  g_Hh);  cudaGetSymbolAddress((void**)&Hl,  g_Hl);

    // 0) pack operands
    pack_f16hl_kernel<<<(NROWS * DIMN / 4 + 255) / 256, 256>>>(X, Xh, Xl, NROWS * DIMN / 4);
    pack_f16_kernel<<<(ZXW * DIMN / 4 + 255) / 256, 256>>>(in_proj_w, Wih, ZXW * DIMN / 4);
    pack_f16_kernel<<<(DIMN * DINNER / 4 + 255) / 256, 256>>>(out_proj_w, Woh, DIMN * DINNER / 4);
    pack_f16_kernel<<<(DINNER * DIMN / 4 + 255) / 256, 256>>>(to_h_w, Wth, DINNER * DIMN / 4);

    // 1) z|xBC = X @ in_proj_w[0:4224]^T  (fp16 2-MMA)
    gemm_f16<0><<<dim3(ZXW / 128, NROWS / 128), 256>>>(
        Xh, Xl, Wih, zx, nullptr, nullptr, NROWS, ZXW, DIMN);
    // 2) dt = softplus(X . Wi_dt + bias)  (fp32 exact)
    dt_gemv_kernel<<<NROWS, 256>>>(X, in_proj_w, dt_bias);
    // 3) conv + silu
    conv_silu_kernel<<<(int)(((size_t)NROWS * CONVD + 255) / 256), 256>>>(conv_w, conv_b);
    // 4) segmented scan
    scan_seg_kernel<<<BATCHN * NHEADSN * NSEG, 256>>>(A_log);
    state_combine_kernel<<<BATCHN * NHEADSN, 256>>>();
    carry_mma_kernel<<<BATCHN * NHEADSN * (NSEG - 1), 256>>>();
    // 5) gate + rmsnorm -> packed fp16 yn
    gate_norm_kernel<<<NROWS, 256>>>(Dp, norm_w);
    // 6) H = yn @ out_proj_w^T  (fp16 2-MMA, packed out)
    gemm_f16<1><<<dim3(DIMN / 128, NROWS / 128), 256>>>(
        ynh, ynl, Woh, nullptr, Hh, Hl, NROWS, DIMN, DINNER);
    // 7) HKV = H @ to_h_w^T with fused split  (fp16 2-MMA)
    gemm_f16<2><<<dim3(DINNER / 128, NROWS / 128), 256>>>(
        Hh, Hl, Wth, out, nullptr, nullptr, NROWS, DINNER, DIMN);
}

// round 10
// speedup vs baseline: 1.4281x; 1.2059x over previous
#include <cuda_runtime.h>
#include <cuda_fp16.h>
#include <math.h>
#include <stdint.h>

#define BATCHN 2
#define SEQLENN 4096
#define DIMN 1024
#define DSTATE 64
#define DCONVN 4
#define DINNER 2048
#define NHEADSN 32
#define CONVD 2176          // D_INNER + 2*D_STATE
#define ZXW 4224            // z + xBC columns (dt handled separately); 33*128
#define NROWS (BATCHN*SEQLENN)   // 8192
#define NCH 64              // timesteps per chunk
#define NCHUNK (SEQLENN/NCH)    // 64
#define EPSV 1e-5f

// ------------------------- scratch -------------------------
__device__ float g_zxbcdt[(size_t)NROWS * ZXW];     // z | xBC
__device__ float g_xBCc[(size_t)NROWS * CONVD];
__device__ float g_dt[(size_t)NROWS * NHEADSN];
__device__ float g_y[(size_t)NROWS * DINNER];
__device__ float g_state[(size_t)BATCHN * NHEADSN * NCHUNK * DSTATE * 64];
__device__ float g_hin[(size_t)BATCHN * NHEADSN * NCHUNK * DSTATE * 64];
__device__ float g_acum[(size_t)BATCHN * NHEADSN * SEQLENN];

// packed fp16 operands (uint32 = 2 halves along K)
__device__ uint32_t g_Xh[(size_t)NROWS * (DIMN/2)], g_Xl[(size_t)NROWS * (DIMN/2)];
__device__ uint32_t g_Wih[(size_t)ZXW * (DIMN/2)];
__device__ uint32_t g_Woh[(size_t)DIMN * (DINNER/2)];
__device__ uint32_t g_Wth[(size_t)DINNER * (DIMN/2)];
__device__ uint32_t g_ynh[(size_t)NROWS * (DINNER/2)], g_ynl[(size_t)NROWS * (DINNER/2)];
__device__ uint32_t g_Hh[(size_t)NROWS * (DIMN/2)],    g_Hl[(size_t)NROWS * (DIMN/2)];

// ------------------------- fp16 helpers -------------------------
__device__ __forceinline__ uint32_t packh_hi(float a, float b, float& ra, float& rb) {
    __half2 h = __floats2half2_rn(a, b);
    ra = a - __half2float(__low2half(h));
    rb = b - __half2float(__high2half(h));
    return *(uint32_t*)&h;
}
__device__ __forceinline__ uint32_t packh(float a, float b) {
    __half2 h = __floats2half2_rn(a, b);
    return *(uint32_t*)&h;
}

#define MMA_F16(c, a, b) \
    asm volatile("mma.sync.aligned.m16n8k16.row.col.f32.f16.f16.f32 " \
        "{%0,%1,%2,%3}, {%4,%5,%6,%7}, {%8,%9}, {%0,%1,%2,%3};" \
        : "+f"((c)[0]), "+f"((c)[1]), "+f"((c)[2]), "+f"((c)[3]) \
        : "r"((a)[0]), "r"((a)[1]), "r"((a)[2]), "r"((a)[3]), \
          "r"((b)[0]), "r"((b)[1]))

// ------------------------- fp16 2-MMA GEMM: C[M,N] = (Ah+Al)[M,K] @ Bh[N,K]^T -------------------------
template<int MODE>
__global__ __launch_bounds__(256) void gemm_f16(
    const uint32_t* __restrict__ Ahg, const uint32_t* __restrict__ Alg,
    const uint32_t* __restrict__ Bhg,
    float* __restrict__ Cf, uint32_t* __restrict__ Ch, uint32_t* __restrict__ Cl,
    int M, int N, int K)
{
    __shared__ uint32_t Ah[8][136];
    __shared__ uint32_t Al[8][136];
    __shared__ uint32_t Bh[8][136];

    const int tid  = threadIdx.x;
    const int bm   = blockIdx.y * 128;
    const int bn   = blockIdx.x * 128;
    const int lane = tid & 31;
    const int warp = tid >> 5;
    const int wm   = (warp >> 2) * 64;
    const int wn   = (warp & 3) * 32;
    const int grp  = lane >> 2;
    const int qid  = lane & 3;
    const int K2   = K >> 1;

    const int sr = tid >> 1;
    const int sc = (tid & 1) * 4;
    const size_t aoff = (size_t)(bm + sr) * K2 + sc;
    const size_t boff = (size_t)(bn + sr) * K2 + sc;

    float acc[4][4][4];
#pragma unroll
    for (int i = 0; i < 4; i++)
#pragma unroll
        for (int j = 0; j < 4; j++)
#pragma unroll
            for (int e = 0; e < 4; e++) acc[i][j][e] = 0.f;

    uint4 avh = *(const uint4*)(Ahg + aoff);
    uint4 avl = *(const uint4*)(Alg + aoff);
    uint4 bvh = *(const uint4*)(Bhg + boff);

    for (int kb = 0; kb < K2; kb += 8) {
        Ah[sc + 0][sr] = avh.x; Ah[sc + 1][sr] = avh.y;
        Ah[sc + 2][sr] = avh.z; Ah[sc + 3][sr] = avh.w;
        Al[sc + 0][sr] = avl.x; Al[sc + 1][sr] = avl.y;
        Al[sc + 2][sr] = avl.z; Al[sc + 3][sr] = avl.w;
        Bh[sc + 0][sr] = bvh.x; Bh[sc + 1][sr] = bvh.y;
        Bh[sc + 2][sr] = bvh.z; Bh[sc + 3][sr] = bvh.w;
        __syncthreads();

        if (kb + 8 < K2) {
            avh = *(const uint4*)(Ahg + aoff + kb + 8);
            avl = *(const uint4*)(Alg + aoff + kb + 8);
            bvh = *(const uint4*)(Bhg + boff + kb + 8);
        }

        uint32_t ah[4][4], al[4][4];
#pragma unroll
        for (int mf = 0; mf < 4; mf++) {
            int r0 = wm + mf * 16 + grp;
            ah[mf][0] = Ah[qid    ][r0];
            ah[mf][1] = Ah[qid    ][r0 + 8];
            ah[mf][2] = Ah[qid + 4][r0];
            ah[mf][3] = Ah[qid + 4][r0 + 8];
            al[mf][0] = Al[qid    ][r0];
            al[mf][1] = Al[qid    ][r0 + 8];
            al[mf][2] = Al[qid + 4][r0];
            al[mf][3] = Al[qid + 4][r0 + 8];
        }
        uint32_t bh[4][2];
#pragma unroll
        for (int nf = 0; nf < 4; nf++) {
            int c0 = wn + nf * 8 + grp;
            bh[nf][0] = Bh[qid    ][c0];
            bh[nf][1] = Bh[qid + 4][c0];
        }
#pragma unroll
        for (int mf = 0; mf < 4; mf++)
#pragma unroll
            for (int nf = 0; nf < 4; nf++) {
                MMA_F16(acc[mf][nf], ah[mf], bh[nf]);
                MMA_F16(acc[mf][nf], al[mf], bh[nf]);
            }
        __syncthreads();
    }

#pragma unroll
    for (int mf = 0; mf < 4; mf++) {
        int gr0 = bm + wm + mf * 16 + grp;
        int gr1 = gr0 + 8;
#pragma unroll
        for (int nf = 0; nf < 4; nf++) {
            int gc = bn + wn + nf * 8 + 2 * qid;
            if (MODE == 0) {
                Cf[(size_t)gr0 * N + gc]     = acc[mf][nf][0];
                Cf[(size_t)gr0 * N + gc + 1] = acc[mf][nf][1];
                Cf[(size_t)gr1 * N + gc]     = acc[mf][nf][2];
                Cf[(size_t)gr1 * N + gc + 1] = acc[mf][nf][3];
            } else if (MODE == 1) {
                int kp = gc >> 1;
                float r0, r1;
                Ch[(size_t)gr0 * (N/2) + kp] = packh_hi(acc[mf][nf][0], acc[mf][nf][1], r0, r1);
                Cl[(size_t)gr0 * (N/2) + kp] = packh(r0, r1);
                Ch[(size_t)gr1 * (N/2) + kp] = packh_hi(acc[mf][nf][2], acc[mf][nf][3], r0, r1);
                Cl[(size_t)gr1 * (N/2) + kp] = packh(r0, r1);
            } else {
                size_t off = (gc < DIMN)
                    ? (size_t)gr0 * DIMN + gc
                    : (size_t)NROWS * DIMN + (size_t)gr0 * DIMN + (gc - DIMN);
                Cf[off]     = acc[mf][nf][0];
                Cf[off + 1] = acc[mf][nf][1];
                size_t off1 = off + (size_t)8 * DIMN;
                Cf[off1]     = acc[mf][nf][2];
                Cf[off1 + 1] = acc[mf][nf][3];
            }
        }
    }
}

// ------------------------- pack kernels -------------------------
__global__ void pack_f16_kernel(const float* __restrict__ src, uint32_t* __restrict__ hi, int n4)
{
    int i = blockIdx.x * blockDim.x + threadIdx.x;
    if (i >= n4) return;
    float4 v = ((const float4*)src)[i];
    ((uint2*)hi)[i] = make_uint2(packh(v.x, v.y), packh(v.z, v.w));
}
__global__ void pack_f16hl_kernel(const float* __restrict__ src,
                                  uint32_t* __restrict__ hi, uint32_t* __restrict__ lo, int n4)
{
    int i = blockIdx.x * blockDim.x + threadIdx.x;
    if (i >= n4) return;
    float4 v = ((const float4*)src)[i];
    float r0, r1, r2, r3;
    uint32_t h0 = packh_hi(v.x, v.y, r0, r1);
    uint32_t h1 = packh_hi(v.z, v.w, r2, r3);
    ((uint2*)hi)[i] = make_uint2(h0, h1);
    ((uint2*)lo)[i] = make_uint2(packh(r0, r1), packh(r2, r3));
}

// ------------------------- dt GEMV (fp32 exact) + softplus -------------------------
__global__ __launch_bounds__(256) void dt_gemv_kernel(
    const float* __restrict__ X, const float* __restrict__ Wi, const float* __restrict__ dt_bias)
{
    const int row  = blockIdx.x;
    const int tid  = threadIdx.x;
    const int warp = tid >> 5;
    const int lane = tid & 31;
    __shared__ __align__(16) float sx[DIMN];
    *(float4*)&sx[tid * 4] = *(const float4*)(X + (size_t)row * DIMN + tid * 4);
    __syncthreads();
#pragma unroll
    for (int hh = 0; hh < 4; hh++) {
        int h = warp * 4 + hh;
        const float* w = Wi + (size_t)(ZXW + h) * DIMN;
        float s = 0.f;
#pragma unroll
        for (int i = 0; i < 8; i++) {
            int k = (lane + i * 32) * 4;
            float4 xv = *(const float4*)&sx[k];
            float4 wv = *(const float4*)(w + k);
            s = fmaf(xv.x, wv.x, s); s = fmaf(xv.y, wv.y, s);
            s = fmaf(xv.z, wv.z, s); s = fmaf(xv.w, wv.w, s);
        }
        for (int o = 16; o; o >>= 1) s += __shfl_down_sync(0xffffffffu, s, o);
        if (lane == 0) {
            float v = s + dt_bias[h];
            g_dt[(size_t)row * NHEADSN + h] = (v > 20.f) ? v : log1pf(expf(v));
        }
    }
}

// ------------------------- depthwise causal conv (w=4) + bias + SiLU -------------------------
__global__ void conv_silu_kernel(const float* __restrict__ cw, const float* __restrict__ cb)
{
    size_t idx = (size_t)blockIdx.x * blockDim.x + threadIdx.x;
    if (idx >= (size_t)NROWS * CONVD) return;
    int c = (int)(idx % CONVD);
    size_t bl = idx / CONVD;
    int l = (int)(bl % SEQLENN);
    int b = (int)(bl / SEQLENN);
    float acc = cb[c];
#pragma unroll
    for (int k = 0; k < DCONVN; k++) {
        int lt = l - (DCONVN - 1) + k;
        if (lt >= 0)
            acc = fmaf(cw[c * DCONVN + k],
                       g_zxbcdt[(size_t)(b * SEQLENN + lt) * ZXW + DINNER + c], acc);
    }
    float sg = 1.f / (1.f + expf(-acc));
    g_xBCc[idx] = acc * sg;
}

// ------------------------- pass A: chunked SSD scan via MMA -------------------------
// One block per (b,h,chunk of 64 t). 128 threads / 4 warps, warp owns 16 output rows.
// G = (Ch+Cl)@Bh^T; M = tril(G*exp(cum_t-cum_s)); Y = (Mh+Ml)@Xdh; S = Bdh@Xdh.
__global__ __launch_bounds__(128) void scan_chunk_kernel(const float* __restrict__ A_log)
{
    const int bid   = blockIdx.x;
    const int chunk = bid & (NCHUNK - 1);
    const int h     = (bid >> 6) & (NHEADSN - 1);
    const int b     = bid >> 11;
    const int tid   = threadIdx.x;
    const int warp  = tid >> 5;
    const int lane  = tid & 31;
    const int grp   = lane >> 2;
    const int qid   = lane & 3;
    const float Ahc = -expf(A_log[h]);
    const int bh    = b * NHEADSN + h;
    const int rbase = b * SEQLENN + chunk * NCH;
    const int r0    = warp * 16 + grp;
    const int r1    = r0 + 8;

    __shared__ uint32_t b1h[32][72];   // Ch -> Mh   [kpair][row]
    __shared__ uint32_t b1l[32][72];   // Cl -> Ml
    __shared__ uint32_t b2[32][72];    // Bh -> Bdh
    __shared__ uint32_t b3[32][72];    // Xdh
    __shared__ float sdt[NCH], scum[NCH], seL[NCH];

    if (tid < NCH) sdt[tid] = g_dt[(size_t)(rbase + tid) * NHEADSN + h];
    // C (hi/lo) and B (hi), pairs along n: buf[kp n][row t|s]
#pragma unroll
    for (int it = 0; it < 8; it++) {
        int idx = tid + it * 128;          // 0..1023
        int r   = idx >> 4;                // row 0..63
        int kk  = (idx & 15) << 2;         // n: 0,4,..,60
        size_t ro = (size_t)(rbase + r) * CONVD + DINNER;
        float4 bv = *(const float4*)(g_xBCc + ro + kk);
        float4 cv = *(const float4*)(g_xBCc + ro + DSTATE + kk);
        int sp = kk >> 1;
        float e0, e1;
        b1h[sp    ][r] = packh_hi(cv.x, cv.y, e0, e1); b1l[sp    ][r] = packh(e0, e1);
        b1h[sp + 1][r] = packh_hi(cv.z, cv.w, e0, e1); b1l[sp + 1][r] = packh(e0, e1);
        b2[sp    ][r] = packh(bv.x, bv.y);
        b2[sp + 1][r] = packh(bv.z, bv.w);
    }
    __syncthreads();
    if (tid == 0) {
        float c = 0.f;
#pragma unroll
        for (int t = 0; t < NCH; t++) { c += sdt[t] * Ahc; scum[t] = c; }
    }
    __syncthreads();
    if (tid < NCH) {
        seL[tid] = __expf(scum[NCH - 1] - scum[tid]);
        g_acum[(size_t)bh * SEQLENN + chunk * NCH + tid] = __expf(scum[tid]);
    }
    // Xd[s][p] = dt_s * x_s[p], pairs along s: b3[kp s][p]
#pragma unroll
    for (int it = 0; it < 16; it++) {
        int idx = tid + it * 128;          // 0..2047
        int kp  = idx >> 6;
        int p   = idx & 63;
        size_t ro = (size_t)(rbase + 2 * kp) * CONVD + h * 64 + p;
        float x0 = g_xBCc[ro]          * sdt[2 * kp];
        float x1 = g_xBCc[ro + CONVD]  * sdt[2 * kp + 1];
        b3[kp][p] = packh(x0, x1);
    }
    __syncthreads();

    // G MMA: rows t, cols s, K = n
    float gacc[8][4];
#pragma unroll
    for (int i = 0; i < 8; i++)
#pragma unroll
        for (int e = 0; e < 4; e++) gacc[i][e] = 0.f;
#pragma unroll
    for (int ks = 0; ks < 4; ks++) {
        uint32_t ah[4], al[4];
        ah[0] = b1h[ks*8+qid  ][r0]; ah[1] = b1h[ks*8+qid  ][r1];
        ah[2] = b1h[ks*8+qid+4][r0]; ah[3] = b1h[ks*8+qid+4][r1];
        al[0] = b1l[ks*8+qid  ][r0]; al[1] = b1l[ks*8+qid  ][r1];
        al[2] = b1l[ks*8+qid+4][r0]; al[3] = b1l[ks*8+qid+4][r1];
#pragma unroll
        for (int nf = 0; nf < 8; nf++) {
            int c0 = nf * 8 + grp;
            uint32_t bb[2] = { b2[ks*8+qid][c0], b2[ks*8+qid+4][c0] };
            MMA_F16(gacc[nf], ah, bb);
            MMA_F16(gacc[nf], al, bb);
        }
    }
    __syncthreads();

    // M = tril(G * exp(cum_t - cum_s)) -> pack into b1h/b1l as [kp s][t]
#pragma unroll
    for (int nf = 0; nf < 8; nf++) {
        int s0 = nf * 8 + 2 * qid;
        float m0 = (s0     <= r0) ? gacc[nf][0] * __expf(scum[r0] - scum[s0    ]) : 0.f;
        float m1 = (s0 + 1 <= r0) ? gacc[nf][1] * __expf(scum[r0] - scum[s0 + 1]) : 0.f;
        float m2 = (s0     <= r1) ? gacc[nf][2] * __expf(scum[r1] - scum[s0    ]) : 0.f;
        float m3 = (s0 + 1 <= r1) ? gacc[nf][3] * __expf(scum[r1] - scum[s0 + 1]) : 0.f;
        int kp = nf * 4 + qid;
        float e0, e1;
        uint32_t h0 = packh_hi(m0, m1, e0, e1); uint32_t l0 = packh(e0, e1);
        uint32_t h1 = packh_hi(m2, m3, e0, e1); uint32_t l1 = packh(e0, e1);
        b1h[kp][r0] = h0; b1l[kp][r0] = l0;
        b1h[kp][r1] = h1; b1l[kp][r1] = l1;
    }
    // Bd[s][n] = B[s][n] * eL[s] -> b2 as [kp s][n]  (b2 free after G MMA + sync)
#pragma unroll
    for (int it = 0; it < 16; it++) {
        int idx = tid + it * 128;
        int kp  = idx >> 6;
        int n   = idx & 63;
        size_t ro = (size_t)(rbase + 2 * kp) * CONVD + DINNER + n;
        float v0 = g_xBCc[ro]         * seL[2 * kp];
        float v1 = g_xBCc[ro + CONVD] * seL[2 * kp + 1];
        b2[kp][n] = packh(v0, v1);
    }
    __syncthreads();

    // Y = (Mh+Ml)@Xdh ; S = Bdh@Xdh   (K = s)
    float yacc[8][4], sacc[8][4];
#pragma unroll
    for (int i = 0; i < 8; i++)
#pragma unroll
        for (int e = 0; e < 4; e++) { yacc[i][e] = 0.f; sacc[i][e] = 0.f; }
#pragma unroll
    for (int ks = 0; ks < 4; ks++) {
        uint32_t mh[4], ml[4], sh[4];
        mh[0] = b1h[ks*8+qid  ][r0]; mh[1] = b1h[ks*8+qid  ][r1];
        mh[2] = b1h[ks*8+qid+4][r0]; mh[3] = b1h[ks*8+qid+4][r1];
        ml[0] = b1l[ks*8+qid  ][r0]; ml[1] = b1l[ks*8+qid  ][r1];
        ml[2] = b1l[ks*8+qid+4][r0]; ml[3] = b1l[ks*8+qid+4][r1];
        sh[0] = b2[ks*8+qid  ][r0];  sh[1] = b2[ks*8+qid  ][r1];
        sh[2] = b2[ks*8+qid+4][r0];  sh[3] = b2[ks*8+qid+4][r1];
#pragma unroll
        for (int nf = 0; nf < 8; nf++) {
            int c0 = nf * 8 + grp;
            uint32_t bb[2] = { b3[ks*8+qid][c0], b3[ks*8+qid+4][c0] };
            MMA_F16(yacc[nf], mh, bb);
            MMA_F16(yacc[nf], ml, bb);
            MMA_F16(sacc[nf], sh, bb);
        }
    }

    const size_t sbase = (size_t)(bh * NCHUNK + chunk) * (64 * DSTATE);
#pragma unroll
    for (int nf = 0; nf < 8; nf++) {
        int p0 = nf * 8 + 2 * qid;
        size_t y0 = (size_t)(rbase + r0) * DINNER + h * 64 + p0;
        size_t y1 = (size_t)(rbase + r1) * DINNER + h * 64 + p0;
        g_y[y0]     = yacc[nf][0];
        g_y[y0 + 1] = yacc[nf][1];
        g_y[y1]     = yacc[nf][2];
        g_y[y1 + 1] = yacc[nf][3];
        g_state[sbase + (size_t)r0 * 64 + p0]     = sacc[nf][0];
        g_state[sbase + (size_t)r0 * 64 + p0 + 1] = sacc[nf][1];
        g_state[sbase + (size_t)r1 * 64 + p0]     = sacc[nf][2];
        g_state[sbase + (size_t)r1 * 64 + p0 + 1] = sacc[nf][3];
    }
}

// ------------------------- pass B: prefix over chunk states -------------------------
__global__ __launch_bounds__(256) void state_combine_kernel()
{
    const int bh = blockIdx.x;
    const int tid = threadIdx.x;
    const size_t base = (size_t)bh * NCHUNK * (64 * DSTATE);
    float4 hin[4];
#pragma unroll
    for (int q = 0; q < 4; q++) hin[q] = make_float4(0.f, 0.f, 0.f, 0.f);

    for (int c = 1; c < NCHUNK; c++) {
        float ap = g_acum[(size_t)bh * SEQLENN + c * NCH - 1];
        const float4* sl = (const float4*)(g_state + base + (size_t)(c - 1) * (64 * DSTATE) + tid * 16);
        float4* ho = (float4*)(g_hin + base + (size_t)c * (64 * DSTATE) + tid * 16);
#pragma unroll
        for (int q = 0; q < 4; q++) {
            float4 s = sl[q];
            hin[q].x = fmaf(hin[q].x, ap, s.x);
            hin[q].y = fmaf(hin[q].y, ap, s.y);
            hin[q].z = fmaf(hin[q].z, ap, s.z);
            hin[q].w = fmaf(hin[q].w, ap, s.w);
            ho[q] = hin[q];
        }
    }
}

// ------------------------- pass C: y += (C .* L) @ S_in^T -------------------------
__global__ __launch_bounds__(128) void carry_mma_kernel()
{
    const int bid   = blockIdx.x;
    const int chunk = 1 + (bid % (NCHUNK - 1));
    const int bh    = bid / (NCHUNK - 1);
    const int h     = bh & (NHEADSN - 1);
    const int b     = bh >> 5;
    const int tid   = threadIdx.x;
    const int warp  = tid >> 5;
    const int lane  = tid & 31;
    const int grp   = lane >> 2;
    const int qid   = lane & 3;
    const int rbase = b * SEQLENN + chunk * NCH;
    const int r0    = warp * 16 + grp;
    const int r1    = r0 + 8;

    __shared__ uint32_t ach[32][72];
    __shared__ uint32_t acl[32][72];
    __shared__ uint32_t sbb[32][72];

    // A = C[t][n] * L_t, pairs along n
#pragma unroll
    for (int it = 0; it < 8; it++) {
        int idx = tid + it * 128;
        int r   = idx >> 4;
        int kk  = (idx & 15) << 2;
        float Lt = g_acum[(size_t)bh * SEQLENN + chunk * NCH + r];
        float4 cv = *(const float4*)(g_xBCc + (size_t)(rbase + r) * CONVD + DINNER + DSTATE + kk);
        cv.x *= Lt; cv.y *= Lt; cv.z *= Lt; cv.w *= Lt;
        int sp = kk >> 1;
        float e0, e1;
        ach[sp    ][r] = packh_hi(cv.x, cv.y, e0, e1); acl[sp    ][r] = packh(e0, e1);
        ach[sp + 1][r] = packh_hi(cv.z, cv.w, e0, e1); acl[sp + 1][r] = packh(e0, e1);
    }
    // B = S_in[n][p] -> [kp n][p]
    {
        const float* si = g_hin + (size_t)(bh * NCHUNK + chunk) * (64 * DSTATE);
#pragma unroll
        for (int it = 0; it < 16; it++) {
            int idx = tid + it * 128;
            int kp  = idx >> 6;
            int p   = idx & 63;
            float s0 = si[(size_t)(2 * kp) * 64 + p];
            float s1 = si[(size_t)(2 * kp + 1) * 64 + p];
            sbb[kp][p] = packh(s0, s1);
        }
    }
    __syncthreads();

    float yacc[8][4];
#pragma unroll
    for (int i = 0; i < 8; i++)
#pragma unroll
        for (int e = 0; e < 4; e++) yacc[i][e] = 0.f;
#pragma unroll
    for (int ks = 0; ks < 4; ks++) {
        uint32_t ah[4], al[4];
        ah[0] = ach[ks*8+qid  ][r0]; ah[1] = ach[ks*8+qid  ][r1];
        ah[2] = ach[ks*8+qid+4][r0]; ah[3] = ach[ks*8+qid+4][r1];
        al[0] = acl[ks*8+qid  ][r0]; al[1] = acl[ks*8+qid  ][r1];
        al[2] = acl[ks*8+qid+4][r0]; al[3] = acl[ks*8+qid+4][r1];
#pragma unroll
        for (int nf = 0; nf < 8; nf++) {
            int c0 = nf * 8 + grp;
            uint32_t bb[2] = { sbb[ks*8+qid][c0], sbb[ks*8+qid+4][c0] };
            MMA_F16(yacc[nf], ah, bb);
            MMA_F16(yacc[nf], al, bb);
        }
    }

#pragma unroll
    for (int nf = 0; nf < 8; nf++) {
        int p0 = nf * 8 + 2 * qid;
        size_t y0 = (size_t)(rbase + r0) * DINNER + h * 64 + p0;
        size_t y1 = (size_t)(rbase + r1) * DINNER + h * 64 + p0;
        g_y[y0]     += yacc[nf][0];
        g_y[y0 + 1] += yacc[nf][1];
        g_y[y1]     += yacc[nf][2];
        g_y[y1 + 1] += yacc[nf][3];
    }
}

// ------------------------- D*x, gate, RMSNorm -> packed fp16 hi/lo -------------------------
__global__ __launch_bounds__(256) void gate_norm_kernel(
    const float* __restrict__ Dp, const float* __restrict__ norm_w)
{
    const int row = blockIdx.x;
    const int tid = threadIdx.x;
    const int c0 = tid * 8;
    const int hh = c0 >> 6;

    float vals[8];
    float ss = 0.f;
    {
        const float4* yv = (const float4*)(g_y + (size_t)row * DINNER + c0);
        const float4* xv = (const float4*)(g_xBCc + (size_t)row * CONVD + c0);
        const float4* zv = (const float4*)(g_zxbcdt + (size_t)row * ZXW + c0);
        float Dh = Dp[hh];
#pragma unroll
        for (int q = 0; q < 2; q++) {
            float4 y = yv[q], x = xv[q], z = zv[q];
            float a[4] = {y.x, y.y, y.z, y.w};
            float bb[4] = {x.x, x.y, x.z, x.w};
            float g[4] = {z.x, z.y, z.z, z.w};
#pragma unroll
            for (int e = 0; e < 4; e++) {
                float yy = fmaf(Dh, bb[e], a[e]);
                float gg = g[e] / (1.f + expf(-g[e]));
                float v = yy * gg;
                vals[q * 4 + e] = v;
                ss = fmaf(v, v, ss);
            }
        }
    }
    __shared__ float red[32];
    for (int o = 16; o; o >>= 1) ss += __shfl_down_sync(0xffffffffu, ss, o);
    if ((tid & 31) == 0) red[tid >> 5] = ss;
    __syncthreads();
    if (tid < 32) {
        float s2 = (tid < 8) ? red[tid] : 0.f;
        for (int o = 4; o; o >>= 1) s2 += __shfl_down_sync(0xffffffffu, s2, o);
        if (tid == 0) red[0] = s2;
    }
    __syncthreads();
    float scale = rsqrtf(red[0] / (float)DINNER + EPSV);

    uint32_t ho[4], lo[4];
#pragma unroll
    for (int j = 0; j < 4; j++) {
        float a = vals[2*j]     * scale * norm_w[c0 + 2*j];
        float bv = vals[2*j + 1] * scale * norm_w[c0 + 2*j + 1];
        float r0, r1;
        ho[j] = packh_hi(a, bv, r0, r1);
        lo[j] = packh(r0, r1);
    }
    *(uint4*)(g_ynh + (size_t)row * (DINNER/2) + tid * 4) = *(uint4*)ho;
    *(uint4*)(g_ynl + (size_t)row * (DINNER/2) + tid * 4) = *(uint4*)lo;
}

// ------------------------- launch -------------------------
extern "C" void kernel_launch(void* const* d_in, const int* in_sizes, int n_in,
                              void* d_out, int out_size)
{
    const float* X          = (const float*)d_in[0];
    const float* in_proj_w  = (const float*)d_in[1];
    const float* conv_w     = (const float*)d_in[2];
    const float* conv_b     = (const float*)d_in[3];
    const float* dt_bias    = (const float*)d_in[4];
    const float* A_log      = (const float*)d_in[5];
    const float* Dp         = (const float*)d_in[6];
    const float* norm_w     = (const float*)d_in[7];
    const float* out_proj_w = (const float*)d_in[8];
    const float* to_h_w     = (const float*)d_in[9];
    float* out = (float*)d_out;

    float *zx;
    uint32_t *Xh, *Xl, *Wih, *Woh, *Wth, *ynh, *ynl, *Hh, *Hl;
    cudaGetSymbolAddress((void**)&zx,  g_zxbcdt);
    cudaGetSymbolAddress((void**)&Xh,  g_Xh);  cudaGetSymbolAddress((void**)&Xl,  g_Xl);
    cudaGetSymbolAddress((void**)&Wih, g_Wih);
    cudaGetSymbolAddress((void**)&Woh, g_Woh);
    cudaGetSymbolAddress((void**)&Wth, g_Wth);
    cudaGetSymbolAddress((void**)&ynh, g_ynh); cudaGetSymbolAddress((void**)&ynl, g_ynl);
    cudaGetSymbolAddress((void**)&Hh,  g_Hh);  cudaGetSymbolAddress((void**)&Hl,  g_Hl);

    // 0) pack operands
    pack_f16hl_kernel<<<(NROWS * DIMN / 4 + 255) / 256, 256>>>(X, Xh, Xl, NROWS * DIMN / 4);
    pack_f16_kernel<<<(ZXW * DIMN / 4 + 255) / 256, 256>>>(in_proj_w, Wih, ZXW * DIMN / 4);
    pack_f16_kernel<<<(DIMN * DINNER / 4 + 255) / 256, 256>>>(out_proj_w, Woh, DIMN * DINNER / 4);
    pack_f16_kernel<<<(DINNER * DIMN / 4 + 255) / 256, 256>>>(to_h_w, Wth, DINNER * DIMN / 4);

    // 1) z|xBC = X @ in_proj_w[0:4224]^T  (fp16 2-MMA)
    gemm_f16<0><<<dim3(ZXW / 128, NROWS / 128), 256>>>(
        Xh, Xl, Wih, zx, nullptr, nullptr, NROWS, ZXW, DIMN);
    // 2) dt = softplus(X . Wi_dt + bias)  (fp32 exact)
    dt_gemv_kernel<<<NROWS, 256>>>(X, in_proj_w, dt_bias);
    // 3) conv + silu
    conv_silu_kernel<<<(int)(((size_t)NROWS * CONVD + 255) / 256), 256>>>(conv_w, conv_b);
    // 4) chunked SSD scan: local MMA pass, state prefix, carry MMA
    scan_chunk_kernel<<<BATCHN * NHEADSN * NCHUNK, 128>>>(A_log);
    state_combine_kernel<<<BATCHN * NHEADSN, 256>>>();
    carry_mma_kernel<<<BATCHN * NHEADSN * (NCHUNK - 1), 128>>>();
    // 5) gate + rmsnorm -> packed fp16 yn
    gate_norm_kernel<<<NROWS, 256>>>(Dp, norm_w);
    // 6) H = yn @ out_proj_w^T  (fp16 2-MMA, packed out)
    gemm_f16<1><<<dim3(DIMN / 128, NROWS / 128), 256>>>(
        ynh, ynl, Woh, nullptr, Hh, Hl, NROWS, DIMN, DINNER);
    // 7) HKV = H @ to_h_w^T with fused split  (fp16 2-MMA)
    gemm_f16<2><<<dim3(DINNER / 128, NROWS / 128), 256>>>(
        Hh, Hl, Wth, out, nullptr, nullptr, NROWS, DINNER, DIMN);
}

// round 11
// speedup vs baseline: 2.1814x; 1.5275x over previous
#include <cuda_runtime.h>
#include <cuda_fp16.h>
#include <math.h>
#include <stdint.h>

#define BATCHN 2
#define SEQLENN 4096
#define DIMN 1024
#define DSTATE 64
#define DCONVN 4
#define DINNER 2048
#define NHEADSN 32
#define CONVD 2176          // D_INNER + 2*D_STATE
#define ZXW 4224            // z + xBC columns (dt handled separately); 33*128
#define NROWS (BATCHN*SEQLENN)   // 8192
#define NCH 64              // timesteps per chunk
#define NCHUNK (SEQLENN/NCH)    // 64
#define EPSV 1e-5f

// ------------------------- scratch -------------------------
__device__ float g_zxbcdt[(size_t)NROWS * ZXW];     // z | xBC
__device__ float g_xBCc[(size_t)NROWS * CONVD];
__device__ float g_dt[(size_t)NROWS * NHEADSN];
__device__ float g_y[(size_t)NROWS * DINNER];
__device__ float g_state[(size_t)BATCHN * NHEADSN * NCHUNK * DSTATE * 64];
__device__ float g_hin[(size_t)BATCHN * NHEADSN * NCHUNK * DSTATE * 64];
__device__ float g_acum[(size_t)BATCHN * NHEADSN * SEQLENN];

// packed fp16 operands (uint32 = 2 halves along K)
__device__ uint32_t g_Xh[(size_t)NROWS * (DIMN/2)];
__device__ uint32_t g_Wih[(size_t)ZXW * (DIMN/2)];
__device__ uint32_t g_Woh[(size_t)DIMN * (DINNER/2)];
__device__ uint32_t g_Wth[(size_t)DINNER * (DIMN/2)];
__device__ uint32_t g_ynh[(size_t)NROWS * (DINNER/2)];
__device__ uint32_t g_Hh[(size_t)NROWS * (DIMN/2)];

// ------------------------- fp16 helpers -------------------------
__device__ __forceinline__ uint32_t packh_hi(float a, float b, float& ra, float& rb) {
    __half2 h = __floats2half2_rn(a, b);
    ra = a - __half2float(__low2half(h));
    rb = b - __half2float(__high2half(h));
    return *(uint32_t*)&h;
}
__device__ __forceinline__ uint32_t packh(float a, float b) {
    __half2 h = __floats2half2_rn(a, b);
    return *(uint32_t*)&h;
}

#define MMA_F16(c, a, b) \
    asm volatile("mma.sync.aligned.m16n8k16.row.col.f32.f16.f16.f32 " \
        "{%0,%1,%2,%3}, {%4,%5,%6,%7}, {%8,%9}, {%0,%1,%2,%3};" \
        : "+f"((c)[0]), "+f"((c)[1]), "+f"((c)[2]), "+f"((c)[3]) \
        : "r"((a)[0]), "r"((a)[1]), "r"((a)[2]), "r"((a)[3]), \
          "r"((b)[0]), "r"((b)[1]))

// ------------------------- pure fp16 GEMM: C[M,N] = Ah[M,K] @ Bh[N,K]^T -------------------------
// MODE 0: f32 C (N multiple of 128).  MODE 1: packed fp16 C.  MODE 2: f32 out with HK|HV split.
template<int MODE>
__global__ __launch_bounds__(256) void gemm_f16(
    const uint32_t* __restrict__ Ahg, const uint32_t* __restrict__ Bhg,
    float* __restrict__ Cf, uint32_t* __restrict__ Ch,
    int M, int N, int K)
{
    __shared__ uint32_t Ah[8][136];
    __shared__ uint32_t Bh[8][136];

    const int tid  = threadIdx.x;
    const int bm   = blockIdx.y * 128;
    const int bn   = blockIdx.x * 128;
    const int lane = tid & 31;
    const int warp = tid >> 5;
    const int wm   = (warp >> 2) * 64;
    const int wn   = (warp & 3) * 32;
    const int grp  = lane >> 2;
    const int qid  = lane & 3;
    const int K2   = K >> 1;

    const int sr = tid >> 1;
    const int sc = (tid & 1) * 4;
    const size_t aoff = (size_t)(bm + sr) * K2 + sc;
    const size_t boff = (size_t)(bn + sr) * K2 + sc;

    float acc[4][4][4];
#pragma unroll
    for (int i = 0; i < 4; i++)
#pragma unroll
        for (int j = 0; j < 4; j++)
#pragma unroll
            for (int e = 0; e < 4; e++) acc[i][j][e] = 0.f;

    uint4 avh = *(const uint4*)(Ahg + aoff);
    uint4 bvh = *(const uint4*)(Bhg + boff);

    for (int kb = 0; kb < K2; kb += 8) {
        Ah[sc + 0][sr] = avh.x; Ah[sc + 1][sr] = avh.y;
        Ah[sc + 2][sr] = avh.z; Ah[sc + 3][sr] = avh.w;
        Bh[sc + 0][sr] = bvh.x; Bh[sc + 1][sr] = bvh.y;
        Bh[sc + 2][sr] = bvh.z; Bh[sc + 3][sr] = bvh.w;
        __syncthreads();

        if (kb + 8 < K2) {
            avh = *(const uint4*)(Ahg + aoff + kb + 8);
            bvh = *(const uint4*)(Bhg + boff + kb + 8);
        }

        uint32_t ah[4][4];
#pragma unroll
        for (int mf = 0; mf < 4; mf++) {
            int r0 = wm + mf * 16 + grp;
            ah[mf][0] = Ah[qid    ][r0];
            ah[mf][1] = Ah[qid    ][r0 + 8];
            ah[mf][2] = Ah[qid + 4][r0];
            ah[mf][3] = Ah[qid + 4][r0 + 8];
        }
        uint32_t bh[4][2];
#pragma unroll
        for (int nf = 0; nf < 4; nf++) {
            int c0 = wn + nf * 8 + grp;
            bh[nf][0] = Bh[qid    ][c0];
            bh[nf][1] = Bh[qid + 4][c0];
        }
#pragma unroll
        for (int mf = 0; mf < 4; mf++)
#pragma unroll
            for (int nf = 0; nf < 4; nf++)
                MMA_F16(acc[mf][nf], ah[mf], bh[nf]);
        __syncthreads();
    }

#pragma unroll
    for (int mf = 0; mf < 4; mf++) {
        int gr0 = bm + wm + mf * 16 + grp;
        int gr1 = gr0 + 8;
#pragma unroll
        for (int nf = 0; nf < 4; nf++) {
            int gc = bn + wn + nf * 8 + 2 * qid;
            if (MODE == 0) {
                Cf[(size_t)gr0 * N + gc]     = acc[mf][nf][0];
                Cf[(size_t)gr0 * N + gc + 1] = acc[mf][nf][1];
                Cf[(size_t)gr1 * N + gc]     = acc[mf][nf][2];
                Cf[(size_t)gr1 * N + gc + 1] = acc[mf][nf][3];
            } else if (MODE == 1) {
                int kp = gc >> 1;
                Ch[(size_t)gr0 * (N/2) + kp] = packh(acc[mf][nf][0], acc[mf][nf][1]);
                Ch[(size_t)gr1 * (N/2) + kp] = packh(acc[mf][nf][2], acc[mf][nf][3]);
            } else {
                size_t off = (gc < DIMN)
                    ? (size_t)gr0 * DIMN + gc
                    : (size_t)NROWS * DIMN + (size_t)gr0 * DIMN + (gc - DIMN);
                Cf[off]     = acc[mf][nf][0];
                Cf[off + 1] = acc[mf][nf][1];
                size_t off1 = off + (size_t)8 * DIMN;
                Cf[off1]     = acc[mf][nf][2];
                Cf[off1 + 1] = acc[mf][nf][3];
            }
        }
    }
}

// ------------------------- pack kernel -------------------------
__global__ void pack_f16_kernel(const float* __restrict__ src, uint32_t* __restrict__ hi, int n4)
{
    int i = blockIdx.x * blockDim.x + threadIdx.x;
    if (i >= n4) return;
    float4 v = ((const float4*)src)[i];
    ((uint2*)hi)[i] = make_uint2(packh(v.x, v.y), packh(v.z, v.w));
}

// ------------------------- dt GEMV (fp32 exact) + softplus -------------------------
__global__ __launch_bounds__(256) void dt_gemv_kernel(
    const float* __restrict__ X, const float* __restrict__ Wi, const float* __restrict__ dt_bias)
{
    const int row  = blockIdx.x;
    const int tid  = threadIdx.x;
    const int warp = tid >> 5;
    const int lane = tid & 31;
    __shared__ __align__(16) float sx[DIMN];
    *(float4*)&sx[tid * 4] = *(const float4*)(X + (size_t)row * DIMN + tid * 4);
    __syncthreads();
#pragma unroll
    for (int hh = 0; hh < 4; hh++) {
        int h = warp * 4 + hh;
        const float* w = Wi + (size_t)(ZXW + h) * DIMN;
        float s = 0.f;
#pragma unroll
        for (int i = 0; i < 8; i++) {
            int k = (lane + i * 32) * 4;
            float4 xv = *(const float4*)&sx[k];
            float4 wv = *(const float4*)(w + k);
            s = fmaf(xv.x, wv.x, s); s = fmaf(xv.y, wv.y, s);
            s = fmaf(xv.z, wv.z, s); s = fmaf(xv.w, wv.w, s);
        }
        for (int o = 16; o; o >>= 1) s += __shfl_down_sync(0xffffffffu, s, o);
        if (lane == 0) {
            float v = s + dt_bias[h];
            g_dt[(size_t)row * NHEADSN + h] = (v > 20.f) ? v : log1pf(expf(v));
        }
    }
}

// ------------------------- depthwise causal conv (w=4) + bias + SiLU -------------------------
__global__ void conv_silu_kernel(const float* __restrict__ cw, const float* __restrict__ cb)
{
    size_t idx = (size_t)blockIdx.x * blockDim.x + threadIdx.x;
    if (idx >= (size_t)NROWS * CONVD) return;
    int c = (int)(idx % CONVD);
    size_t bl = idx / CONVD;
    int l = (int)(bl % SEQLENN);
    int b = (int)(bl / SEQLENN);
    float acc = cb[c];
#pragma unroll
    for (int k = 0; k < DCONVN; k++) {
        int lt = l - (DCONVN - 1) + k;
        if (lt >= 0)
            acc = fmaf(cw[c * DCONVN + k],
                       g_zxbcdt[(size_t)(b * SEQLENN + lt) * ZXW + DINNER + c], acc);
    }
    float sg = 1.f / (1.f + expf(-acc));
    g_xBCc[idx] = acc * sg;
}

// ------------------------- pass A: chunked SSD scan via MMA -------------------------
__global__ __launch_bounds__(128) void scan_chunk_kernel(const float* __restrict__ A_log)
{
    const int bid   = blockIdx.x;
    const int chunk = bid & (NCHUNK - 1);
    const int h     = (bid >> 6) & (NHEADSN - 1);
    const int b     = bid >> 11;
    const int tid   = threadIdx.x;
    const int warp  = tid >> 5;
    const int lane  = tid & 31;
    const int grp   = lane >> 2;
    const int qid   = lane & 3;
    const float Ahc = -expf(A_log[h]);
    const int bh    = b * NHEADSN + h;
    const int rbase = b * SEQLENN + chunk * NCH;
    const int r0    = warp * 16 + grp;
    const int r1    = r0 + 8;

    __shared__ uint32_t b1h[32][72];   // Ch -> Mh   [kpair][row]
    __shared__ uint32_t b1l[32][72];   // Cl -> Ml
    __shared__ uint32_t b2[32][72];    // Bh -> Bdh
    __shared__ uint32_t b3[32][72];    // Xdh
    __shared__ float sdt[NCH], scum[NCH], seL[NCH];

    if (tid < NCH) sdt[tid] = g_dt[(size_t)(rbase + tid) * NHEADSN + h];
#pragma unroll
    for (int it = 0; it < 8; it++) {
        int idx = tid + it * 128;
        int r   = idx >> 4;
        int kk  = (idx & 15) << 2;
        size_t ro = (size_t)(rbase + r) * CONVD + DINNER;
        float4 bv = *(const float4*)(g_xBCc + ro + kk);
        float4 cv = *(const float4*)(g_xBCc + ro + DSTATE + kk);
        int sp = kk >> 1;
        float e0, e1;
        b1h[sp    ][r] = packh_hi(cv.x, cv.y, e0, e1); b1l[sp    ][r] = packh(e0, e1);
        b1h[sp + 1][r] = packh_hi(cv.z, cv.w, e0, e1); b1l[sp + 1][r] = packh(e0, e1);
        b2[sp    ][r] = packh(bv.x, bv.y);
        b2[sp + 1][r] = packh(bv.z, bv.w);
    }
    __syncthreads();
    if (tid == 0) {
        float c = 0.f;
#pragma unroll
        for (int t = 0; t < NCH; t++) { c += sdt[t] * Ahc; scum[t] = c; }
    }
    __syncthreads();
    if (tid < NCH) {
        seL[tid] = __expf(scum[NCH - 1] - scum[tid]);
        g_acum[(size_t)bh * SEQLENN + chunk * NCH + tid] = __expf(scum[tid]);
    }
#pragma unroll
    for (int it = 0; it < 16; it++) {
        int idx = tid + it * 128;
        int kp  = idx >> 6;
        int p   = idx & 63;
        size_t ro = (size_t)(rbase + 2 * kp) * CONVD + h * 64 + p;
        float x0 = g_xBCc[ro]          * sdt[2 * kp];
        float x1 = g_xBCc[ro + CONVD]  * sdt[2 * kp + 1];
        b3[kp][p] = packh(x0, x1);
    }
    __syncthreads();

    float gacc[8][4];
#pragma unroll
    for (int i = 0; i < 8; i++)
#pragma unroll
        for (int e = 0; e < 4; e++) gacc[i][e] = 0.f;
#pragma unroll
    for (int ks = 0; ks < 4; ks++) {
        uint32_t ah[4], al[4];
        ah[0] = b1h[ks*8+qid  ][r0]; ah[1] = b1h[ks*8+qid  ][r1];
        ah[2] = b1h[ks*8+qid+4][r0]; ah[3] = b1h[ks*8+qid+4][r1];
        al[0] = b1l[ks*8+qid  ][r0]; al[1] = b1l[ks*8+qid  ][r1];
        al[2] = b1l[ks*8+qid+4][r0]; al[3] = b1l[ks*8+qid+4][r1];
#pragma unroll
        for (int nf = 0; nf < 8; nf++) {
            int c0 = nf * 8 + grp;
            uint32_t bb[2] = { b2[ks*8+qid][c0], b2[ks*8+qid+4][c0] };
            MMA_F16(gacc[nf], ah, bb);
            MMA_F16(gacc[nf], al, bb);
        }
    }
    __syncthreads();

#pragma unroll
    for (int nf = 0; nf < 8; nf++) {
        int s0 = nf * 8 + 2 * qid;
        float m0 = (s0     <= r0) ? gacc[nf][0] * __expf(scum[r0] - scum[s0    ]) : 0.f;
        float m1 = (s0 + 1 <= r0) ? gacc[nf][1] * __expf(scum[r0] - scum[s0 + 1]) : 0.f;
        float m2 = (s0     <= r1) ? gacc[nf][2] * __expf(scum[r1] - scum[s0    ]) : 0.f;
        float m3 = (s0 + 1 <= r1) ? gacc[nf][3] * __expf(scum[r1] - scum[s0 + 1]) : 0.f;
        int kp = nf * 4 + qid;
        float e0, e1;
        uint32_t h0 = packh_hi(m0, m1, e0, e1); uint32_t l0 = packh(e0, e1);
        uint32_t h1 = packh_hi(m2, m3, e0, e1); uint32_t l1 = packh(e0, e1);
        b1h[kp][r0] = h0; b1l[kp][r0] = l0;
        b1h[kp][r1] = h1; b1l[kp][r1] = l1;
    }
#pragma unroll
    for (int it = 0; it < 16; it++) {
        int idx = tid + it * 128;
        int kp  = idx >> 6;
        int n   = idx & 63;
        size_t ro = (size_t)(rbase + 2 * kp) * CONVD + DINNER + n;
        float v0 = g_xBCc[ro]         * seL[2 * kp];
        float v1 = g_xBCc[ro + CONVD] * seL[2 * kp + 1];
        b2[kp][n] = packh(v0, v1);
    }
    __syncthreads();

    float yacc[8][4], sacc[8][4];
#pragma unroll
    for (int i = 0; i < 8; i++)
#pragma unroll
        for (int e = 0; e < 4; e++) { yacc[i][e] = 0.f; sacc[i][e] = 0.f; }
#pragma unroll
    for (int ks = 0; ks < 4; ks++) {
        uint32_t mh[4], ml[4], sh[4];
        mh[0] = b1h[ks*8+qid  ][r0]; mh[1] = b1h[ks*8+qid  ][r1];
        mh[2] = b1h[ks*8+qid+4][r0]; mh[3] = b1h[ks*8+qid+4][r1];
        ml[0] = b1l[ks*8+qid  ][r0]; ml[1] = b1l[ks*8+qid  ][r1];
        ml[2] = b1l[ks*8+qid+4][r0]; ml[3] = b1l[ks*8+qid+4][r1];
        sh[0] = b2[ks*8+qid  ][r0];  sh[1] = b2[ks*8+qid  ][r1];
        sh[2] = b2[ks*8+qid+4][r0];  sh[3] = b2[ks*8+qid+4][r1];
#pragma unroll
        for (int nf = 0; nf < 8; nf++) {
            int c0 = nf * 8 + grp;
            uint32_t bb[2] = { b3[ks*8+qid][c0], b3[ks*8+qid+4][c0] };
            MMA_F16(yacc[nf], mh, bb);
            MMA_F16(yacc[nf], ml, bb);
            MMA_F16(sacc[nf], sh, bb);
        }
    }

    const size_t sbase = (size_t)(bh * NCHUNK + chunk) * (64 * DSTATE);
#pragma unroll
    for (int nf = 0; nf < 8; nf++) {
        int p0 = nf * 8 + 2 * qid;
        size_t y0 = (size_t)(rbase + r0) * DINNER + h * 64 + p0;
        size_t y1 = (size_t)(rbase + r1) * DINNER + h * 64 + p0;
        g_y[y0]     = yacc[nf][0];
        g_y[y0 + 1] = yacc[nf][1];
        g_y[y1]     = yacc[nf][2];
        g_y[y1 + 1] = yacc[nf][3];
        g_state[sbase + (size_t)r0 * 64 + p0]     = sacc[nf][0];
        g_state[sbase + (size_t)r0 * 64 + p0 + 1] = sacc[nf][1];
        g_state[sbase + (size_t)r1 * 64 + p0]     = sacc[nf][2];
        g_state[sbase + (size_t)r1 * 64 + p0 + 1] = sacc[nf][3];
    }
}

// ------------------------- pass B: prefix over chunk states -------------------------
__global__ __launch_bounds__(256) void state_combine_kernel()
{
    const int bh = blockIdx.x;
    const int tid = threadIdx.x;
    const size_t base = (size_t)bh * NCHUNK * (64 * DSTATE);
    float4 hin[4];
#pragma unroll
    for (int q = 0; q < 4; q++) hin[q] = make_float4(0.f, 0.f, 0.f, 0.f);

    for (int c = 1; c < NCHUNK; c++) {
        float ap = g_acum[(size_t)bh * SEQLENN + c * NCH - 1];
        const float4* sl = (const float4*)(g_state + base + (size_t)(c - 1) * (64 * DSTATE) + tid * 16);
        float4* ho = (float4*)(g_hin + base + (size_t)c * (64 * DSTATE) + tid * 16);
#pragma unroll
        for (int q = 0; q < 4; q++) {
            float4 s = sl[q];
            hin[q].x = fmaf(hin[q].x, ap, s.x);
            hin[q].y = fmaf(hin[q].y, ap, s.y);
            hin[q].z = fmaf(hin[q].z, ap, s.z);
            hin[q].w = fmaf(hin[q].w, ap, s.w);
            ho[q] = hin[q];
        }
    }
}

// ------------------------- pass C: y += (C .* L) @ S_in^T -------------------------
__global__ __launch_bounds__(128) void carry_mma_kernel()
{
    const int bid   = blockIdx.x;
    const int chunk = 1 + (bid % (NCHUNK - 1));
    const int bh    = bid / (NCHUNK - 1);
    const int h     = bh & (NHEADSN - 1);
    const int b     = bh >> 5;
    const int tid   = threadIdx.x;
    const int warp  = tid >> 5;
    const int lane  = tid & 31;
    const int grp   = lane >> 2;
    const int qid   = lane & 3;
    const int rbase = b * SEQLENN + chunk * NCH;
    const int r0    = warp * 16 + grp;
    const int r1    = r0 + 8;

    __shared__ uint32_t ach[32][72];
    __shared__ uint32_t acl[32][72];
    __shared__ uint32_t sbb[32][72];

#pragma unroll
    for (int it = 0; it < 8; it++) {
        int idx = tid + it * 128;
        int r   = idx >> 4;
        int kk  = (idx & 15) << 2;
        float Lt = g_acum[(size_t)bh * SEQLENN + chunk * NCH + r];
        float4 cv = *(const float4*)(g_xBCc + (size_t)(rbase + r) * CONVD + DINNER + DSTATE + kk);
        cv.x *= Lt; cv.y *= Lt; cv.z *= Lt; cv.w *= Lt;
        int sp = kk >> 1;
        float e0, e1;
        ach[sp    ][r] = packh_hi(cv.x, cv.y, e0, e1); acl[sp    ][r] = packh(e0, e1);
        ach[sp + 1][r] = packh_hi(cv.z, cv.w, e0, e1); acl[sp + 1][r] = packh(e0, e1);
    }
    {
        const float* si = g_hin + (size_t)(bh * NCHUNK + chunk) * (64 * DSTATE);
#pragma unroll
        for (int it = 0; it < 16; it++) {
            int idx = tid + it * 128;
            int kp  = idx >> 6;
            int p   = idx & 63;
            float s0 = si[(size_t)(2 * kp) * 64 + p];
            float s1 = si[(size_t)(2 * kp + 1) * 64 + p];
            sbb[kp][p] = packh(s0, s1);
        }
    }
    __syncthreads();

    float yacc[8][4];
#pragma unroll
    for (int i = 0; i < 8; i++)
#pragma unroll
        for (int e = 0; e < 4; e++) yacc[i][e] = 0.f;
#pragma unroll
    for (int ks = 0; ks < 4; ks++) {
        uint32_t ah[4], al[4];
        ah[0] = ach[ks*8+qid  ][r0]; ah[1] = ach[ks*8+qid  ][r1];
        ah[2] = ach[ks*8+qid+4][r0]; ah[3] = ach[ks*8+qid+4][r1];
        al[0] = acl[ks*8+qid  ][r0]; al[1] = acl[ks*8+qid  ][r1];
        al[2] = acl[ks*8+qid+4][r0]; al[3] = acl[ks*8+qid+4][r1];
#pragma unroll
        for (int nf = 0; nf < 8; nf++) {
            int c0 = nf * 8 + grp;
            uint32_t bb[2] = { sbb[ks*8+qid][c0], sbb[ks*8+qid+4][c0] };
            MMA_F16(yacc[nf], ah, bb);
            MMA_F16(yacc[nf], al, bb);
        }
    }

#pragma unroll
    for (int nf = 0; nf < 8; nf++) {
        int p0 = nf * 8 + 2 * qid;
        size_t y0 = (size_t)(rbase + r0) * DINNER + h * 64 + p0;
        size_t y1 = (size_t)(rbase + r1) * DINNER + h * 64 + p0;
        g_y[y0]     += yacc[nf][0];
        g_y[y0 + 1] += yacc[nf][1];
        g_y[y1]     += yacc[nf][2];
        g_y[y1 + 1] += yacc[nf][3];
    }
}

// ------------------------- D*x, gate, RMSNorm -> packed fp16 -------------------------
__global__ __launch_bounds__(256) void gate_norm_kernel(
    const float* __restrict__ Dp, const float* __restrict__ norm_w)
{
    const int row = blockIdx.x;
    const int tid = threadIdx.x;
    const int c0 = tid * 8;
    const int hh = c0 >> 6;

    float vals[8];
    float ss = 0.f;
    {
        const float4* yv = (const float4*)(g_y + (size_t)row * DINNER + c0);
        const float4* xv = (const float4*)(g_xBCc + (size_t)row * CONVD + c0);
        const float4* zv = (const float4*)(g_zxbcdt + (size_t)row * ZXW + c0);
        float Dh = Dp[hh];
#pragma unroll
        for (int q = 0; q < 2; q++) {
            float4 y = yv[q], x = xv[q], z = zv[q];
            float a[4] = {y.x, y.y, y.z, y.w};
            float bb[4] = {x.x, x.y, x.z, x.w};
            float g[4] = {z.x, z.y, z.z, z.w};
#pragma unroll
            for (int e = 0; e < 4; e++) {
                float yy = fmaf(Dh, bb[e], a[e]);
                float gg = g[e] / (1.f + expf(-g[e]));
                float v = yy * gg;
                vals[q * 4 + e] = v;
                ss = fmaf(v, v, ss);
            }
        }
    }
    __shared__ float red[32];
    for (int o = 16; o; o >>= 1) ss += __shfl_down_sync(0xffffffffu, ss, o);
    if ((tid & 31) == 0) red[tid >> 5] = ss;
    __syncthreads();
    if (tid < 32) {
        float s2 = (tid < 8) ? red[tid] : 0.f;
        for (int o = 4; o; o >>= 1) s2 += __shfl_down_sync(0xffffffffu, s2, o);
        if (tid == 0) red[0] = s2;
    }
    __syncthreads();
    float scale = rsqrtf(red[0] / (float)DINNER + EPSV);

    uint32_t ho[4];
#pragma unroll
    for (int j = 0; j < 4; j++) {
        float a  = vals[2*j]     * scale * norm_w[c0 + 2*j];
        float bv = vals[2*j + 1] * scale * norm_w[c0 + 2*j + 1];
        ho[j] = packh(a, bv);
    }
    *(uint4*)(g_ynh + (size_t)row * (DINNER/2) + tid * 4) = *(uint4*)ho;
}

// ------------------------- launch -------------------------
extern "C" void kernel_launch(void* const* d_in, const int* in_sizes, int n_in,
                              void* d_out, int out_size)
{
    const float* X          = (const float*)d_in[0];
    const float* in_proj_w  = (const float*)d_in[1];
    const float* conv_w     = (const float*)d_in[2];
    const float* conv_b     = (const float*)d_in[3];
    const float* dt_bias    = (const float*)d_in[4];
    const float* A_log      = (const float*)d_in[5];
    const float* Dp         = (const float*)d_in[6];
    const float* norm_w     = (const float*)d_in[7];
    const float* out_proj_w = (const float*)d_in[8];
    const float* to_h_w     = (const float*)d_in[9];
    float* out = (float*)d_out;

    float *zx;
    uint32_t *Xh, *Wih, *Woh, *Wth, *ynh, *Hh;
    cudaGetSymbolAddress((void**)&zx,  g_zxbcdt);
    cudaGetSymbolAddress((void**)&Xh,  g_Xh);
    cudaGetSymbolAddress((void**)&Wih, g_Wih);
    cudaGetSymbolAddress((void**)&Woh, g_Woh);
    cudaGetSymbolAddress((void**)&Wth, g_Wth);
    cudaGetSymbolAddress((void**)&ynh, g_ynh);
    cudaGetSymbolAddress((void**)&Hh,  g_Hh);

    // 0) pack operands to fp16
    pack_f16_kernel<<<(NROWS * DIMN / 4 + 255) / 256, 256>>>(X, Xh, NROWS * DIMN / 4);
    pack_f16_kernel<<<(ZXW * DIMN / 4 + 255) / 256, 256>>>(in_proj_w, Wih, ZXW * DIMN / 4);
    pack_f16_kernel<<<(DIMN * DINNER / 4 + 255) / 256, 256>>>(out_proj_w, Woh, DIMN * DINNER / 4);
    pack_f16_kernel<<<(DINNER * DIMN / 4 + 255) / 256, 256>>>(to_h_w, Wth, DINNER * DIMN / 4);

    // 1) z|xBC = X @ in_proj_w[0:4224]^T  (pure fp16)
    gemm_f16<0><<<dim3(ZXW / 128, NROWS / 128), 256>>>(
        Xh, Wih, zx, nullptr, NROWS, ZXW, DIMN);
    // 2) dt = softplus(X . Wi_dt + bias)  (fp32 exact)
    dt_gemv_kernel<<<NROWS, 256>>>(X, in_proj_w, dt_bias);
    // 3) conv + silu
    conv_silu_kernel<<<(int)(((size_t)NROWS * CONVD + 255) / 256), 256>>>(conv_w, conv_b);
    // 4) chunked SSD scan: local MMA pass, state prefix, carry MMA
    scan_chunk_kernel<<<BATCHN * NHEADSN * NCHUNK, 128>>>(A_log);
    state_combine_kernel<<<BATCHN * NHEADSN, 256>>>();
    carry_mma_kernel<<<BATCHN * NHEADSN * (NCHUNK - 1), 128>>>();
    // 5) gate + rmsnorm -> packed fp16 yn
    gate_norm_kernel<<<NROWS, 256>>>(Dp, norm_w);
    // 6) H = yn @ out_proj_w^T  (pure fp16, packed out)
    gemm_f16<1><<<dim3(DIMN / 128, NROWS / 128), 256>>>(
        ynh, Woh, nullptr, Hh, NROWS, DIMN, DINNER);
    // 7) HKV = H @ to_h_w^T with fused split  (pure fp16)
    gemm_f16<2><<<dim3(DINNER / 128, NROWS / 128), 256>>>(
        Hh, Wth, out, nullptr, NROWS, DINNER, DIMN);
}